// round 8
// baseline (speedup 1.0000x reference)
#include <cuda_runtime.h>
#include <cuda_fp16.h>

#define NN 100000
#define NE 1000000
#define FIN 128
#define HH 8
#define HF 256
#define CC 16
#define NB_SCAN ((NN + 1023) / 1024)
#define FULL 0xFFFFFFFFu

// ---------------- scratch (static device globals; no allocation) ----------------
__device__ __align__(16) __half g_h1h[NN * HF];   // fp16 features (message gather)
__device__ __align__(16) float g_out1[NN * HF];   // elu(layer-1 output)
__device__ __align__(16) float g_s1s[NN * HH];
__device__ __align__(16) float g_s1d[NN * HH];
__device__ __align__(16) float g_h2[NN * CC];
__device__ float g_s2s[NN];
__device__ float g_s2d[NN];
__device__ __align__(16) float g_w1[NE * HH];     // layer-1 edge weights (CSR order)
__device__ float g_w2[NE];                        // layer-2 edge weights (CSR order)
__device__ int g_deg[NN];
__device__ int g_cur[NN];
__device__ int g_rs[NN + 1];
__device__ int g_csrc[NE];
__device__ int g_pos[NE];                         // edge e -> CSR slot
__device__ int g_bsum[128];

// fast exp on FMA pipe: 2^(v*log2e), degree-6 Taylor for 2^f, exponent via bit insert.
// rel err ~1.5e-5 over |v| <= 20. Avoids MUFU (rt=8) bottleneck: 8M exps -> ~3us.
__device__ __forceinline__ float fast_exp(float v) {
    float t = v * 1.44269504089f;
    float fi = floorf(t);
    float f = t - fi;
    float p = 1.540353e-4f;
    p = fmaf(p, f, 1.333356e-3f);
    p = fmaf(p, f, 9.618129e-3f);
    p = fmaf(p, f, 5.550411e-2f);
    p = fmaf(p, f, 2.402265e-1f);
    p = fmaf(p, f, 6.931472e-1f);
    p = fmaf(p, f, 1.0f);
    int i = (int)fi;
    return p * __int_as_float((i + 127) << 23);
}

// ---------------- CSR construction ----------------
__global__ void k_zero() {
    int i = blockIdx.x * blockDim.x + threadIdx.x;
    if (i < NN) g_deg[i] = 0;
}

__global__ void k_hist(const int* __restrict__ ei) {
    int e = blockIdx.x * blockDim.x + threadIdx.x;
    if (e < NE) atomicAdd(&g_deg[ei[NE + e]], 1);
}

__global__ void k_scanA() {
    __shared__ int s[1024];
    int t = threadIdx.x;
    int i = blockIdx.x * 1024 + t;
    int v = (i < NN) ? g_deg[i] : 0;
    s[t] = v;
    __syncthreads();
    for (int off = 1; off < 1024; off <<= 1) {
        int u = (t >= off) ? s[t - off] : 0;
        __syncthreads();
        s[t] += u;
        __syncthreads();
    }
    if (i < NN) g_rs[i] = s[t] - v;
    if (t == 1023) g_bsum[blockIdx.x] = s[1023];
}

__global__ void k_scanB() {
    __shared__ int s[128];
    int t = threadIdx.x;
    int v = (t < NB_SCAN) ? g_bsum[t] : 0;
    s[t] = v;
    __syncthreads();
    for (int off = 1; off < 128; off <<= 1) {
        int u = (t >= off) ? s[t - off] : 0;
        __syncthreads();
        s[t] += u;
        __syncthreads();
    }
    if (t < NB_SCAN) g_bsum[t] = s[t] - v;
}

__global__ void k_scanC() {
    int i = blockIdx.x * blockDim.x + threadIdx.x;
    if (i < NN) {
        int v = g_rs[i] + g_bsum[i >> 10];
        g_rs[i] = v;
        g_cur[i] = v;                 // seed scatter cursor with absolute offset
    }
    if (i == 0) g_rs[NN] = NE;
}

__global__ void k_scatter(const int* __restrict__ ei) {
    int e = blockIdx.x * blockDim.x + threadIdx.x;
    if (e < NE) {
        int d = ei[NE + e];
        int pos = atomicAdd(&g_cur[d], 1);   // absolute CSR slot directly
        g_csrc[pos] = ei[e];
        g_pos[e] = pos;
    }
}

// ---------------- GEMM1 + score epilogue ----------------
// 128x128 tile, 256 threads, 8x8 micro-kernel, K-tile 32.
// Epilogue: fp16 feature store + per-head attention dots (s1s/s1d) via quad shuffle.
__global__ void __launch_bounds__(256) k_gemm1(const float* __restrict__ x,
                                               const float* __restrict__ W1,
                                               const float* __restrict__ as1,
                                               const float* __restrict__ ad1) {
    __shared__ float Xs[128][33];   // [m][k], padded
    __shared__ __align__(16) float Ws[32][128];  // [k][n]
    int bm = blockIdx.x * 128;
    int bn = blockIdx.y * 128;
    int t = threadIdx.x;
    int tx = t & 15, ty = t >> 4;
    float acc[8][8];
#pragma unroll
    for (int i = 0; i < 8; i++)
#pragma unroll
        for (int j = 0; j < 8; j++) acc[i][j] = 0.f;

#pragma unroll
    for (int kt = 0; kt < 4; kt++) {
#pragma unroll
        for (int it = 0; it < 4; it++) {
            int idx = t + 256 * it;
            int r = idx >> 3, kc = idx & 7;
            int row = bm + r;
            float4 v = (row < NN)
                ? *(const float4*)(x + row * FIN + kt * 32 + kc * 4)
                : make_float4(0.f, 0.f, 0.f, 0.f);
            Xs[r][kc * 4 + 0] = v.x;
            Xs[r][kc * 4 + 1] = v.y;
            Xs[r][kc * 4 + 2] = v.z;
            Xs[r][kc * 4 + 3] = v.w;
        }
#pragma unroll
        for (int it = 0; it < 4; it++) {
            int idx = t + 256 * it;
            int k = idx >> 5, nc = idx & 31;
            *(float4*)&Ws[k][nc * 4] =
                *(const float4*)(W1 + (kt * 32 + k) * HF + bn + nc * 4);
        }
        __syncthreads();

#pragma unroll 8
        for (int k = 0; k < 32; k++) {
            float a[8];
#pragma unroll
            for (int i = 0; i < 8; i++) a[i] = Xs[ty * 8 + i][k];
            float4 b0 = *(const float4*)&Ws[k][tx * 8];
            float4 b1 = *(const float4*)&Ws[k][tx * 8 + 4];
#pragma unroll
            for (int i = 0; i < 8; i++) {
                acc[i][0] += a[i] * b0.x; acc[i][1] += a[i] * b0.y;
                acc[i][2] += a[i] * b0.z; acc[i][3] += a[i] * b0.w;
                acc[i][4] += a[i] * b1.x; acc[i][5] += a[i] * b1.y;
                acc[i][6] += a[i] * b1.z; acc[i][7] += a[i] * b1.w;
            }
        }
        __syncthreads();
    }

    int head = (bn >> 5) + (tx >> 2);
    int fbase = (tx & 3) * 8;
    float av[8], dv[8];
#pragma unroll
    for (int j = 0; j < 8; j++) {
        av[j] = as1[head * 32 + fbase + j];
        dv[j] = ad1[head * 32 + fbase + j];
    }

#pragma unroll
    for (int i = 0; i < 8; i++) {
        int row = bm + ty * 8 + i;
        bool ok = row < NN;
        if (ok) {
            __half2 p[4];
#pragma unroll
            for (int q = 0; q < 4; q++)
                p[q] = __floats2half2_rn(acc[i][2 * q], acc[i][2 * q + 1]);
            *(uint4*)(g_h1h + row * HF + bn + tx * 8) = *(uint4*)p;
        }
        float ss = 0.f, sd = 0.f;
#pragma unroll
        for (int j = 0; j < 8; j++) { ss += acc[i][j] * av[j]; sd += acc[i][j] * dv[j]; }
        ss += __shfl_xor_sync(FULL, ss, 1); sd += __shfl_xor_sync(FULL, sd, 1);
        ss += __shfl_xor_sync(FULL, ss, 2); sd += __shfl_xor_sync(FULL, sd, 2);
        if (ok && (tx & 3) == 0) {
            g_s1s[row * 8 + head] = ss;
            g_s1d[row * 8 + head] = sd;
        }
    }
}

// ---------------- edge weights, layer 1 (no-max softmax numerator) ----------------
__global__ void k_w1(const int* __restrict__ ei) {
    int e = blockIdx.x * blockDim.x + threadIdx.x;
    if (e >= NE) return;
    int s = ei[e], d = ei[NE + e];
    int pos = g_pos[e];
    float4 ss0 = *(const float4*)&g_s1s[s * 8];
    float4 ss1 = *(const float4*)&g_s1s[s * 8 + 4];
    float4 sd0 = *(const float4*)&g_s1d[d * 8];
    float4 sd1 = *(const float4*)&g_s1d[d * 8 + 4];
    float sc[8] = {ss0.x + sd0.x, ss0.y + sd0.y, ss0.z + sd0.z, ss0.w + sd0.w,
                   ss1.x + sd1.x, ss1.y + sd1.y, ss1.z + sd1.z, ss1.w + sd1.w};
    float wv[8];
#pragma unroll
    for (int h = 0; h < 8; h++) {
        float v = sc[h] > 0.f ? sc[h] : 0.2f * sc[h];
        wv[h] = fast_exp(v);
    }
    *(float4*)&g_w1[pos * 8] = make_float4(wv[0], wv[1], wv[2], wv[3]);
    *(float4*)&g_w1[pos * 8 + 4] = make_float4(wv[4], wv[5], wv[6], wv[7]);
}

// ---------------- layer-1 aggregation: warp per dst node, unroll-4, fused sum ----------------
__global__ void __launch_bounds__(256) k_agg1(const float* __restrict__ b1) {
    int gt = blockIdx.x * blockDim.x + threadIdx.x;
    int w = gt >> 5;
    int lane = threadIdx.x & 31;
    if (w >= NN) return;
    int rs = g_rs[w];
    int deg = g_rs[w + 1] - rs;
    int lh = lane & 7;
    int hsub = lane >> 4;

    float sm = 0.f;
    float acc[8] = {0.f, 0.f, 0.f, 0.f, 0.f, 0.f, 0.f, 0.f};
    int j = 0;
    // 4-edge unrolled main loop: 24 independent loads in flight
    for (; j + 4 <= deg; j += 4) {
        int p0 = rs + j, p1 = rs + j + 1, p2 = rs + j + 2, p3 = rs + j + 3;
        int s0 = g_csrc[p0], s1 = g_csrc[p1], s2 = g_csrc[p2], s3 = g_csrc[p3];
        float w0 = g_w1[p0 * 8 + lh];
        float w1 = g_w1[p1 * 8 + lh];
        float w2 = g_w1[p2 * 8 + lh];
        float w3 = g_w1[p3 * 8 + lh];
        sm += (w0 + w1) + (w2 + w3);
        const __half2* hp0 = (const __half2*)(g_h1h + s0 * HF);
        const __half2* hp1 = (const __half2*)(g_h1h + s1 * HF);
        const __half2* hp2 = (const __half2*)(g_h1h + s2 * HF);
        const __half2* hp3 = (const __half2*)(g_h1h + s3 * HF);
#pragma unroll
        for (int k = 0; k < 4; k++) {
            float2 f0 = __half22float2(hp0[k * 32 + lane]);
            float2 f1 = __half22float2(hp1[k * 32 + lane]);
            float2 f2 = __half22float2(hp2[k * 32 + lane]);
            float2 f3 = __half22float2(hp3[k * 32 + lane]);
            float wk0 = __shfl_sync(FULL, w0, k * 2 + hsub);
            float wk1 = __shfl_sync(FULL, w1, k * 2 + hsub);
            float wk2 = __shfl_sync(FULL, w2, k * 2 + hsub);
            float wk3 = __shfl_sync(FULL, w3, k * 2 + hsub);
            acc[2 * k]     += wk0 * f0.x + wk1 * f1.x + wk2 * f2.x + wk3 * f3.x;
            acc[2 * k + 1] += wk0 * f0.y + wk1 * f1.y + wk2 * f2.y + wk3 * f3.y;
        }
    }
    for (; j < deg; j++) {
        int p0 = rs + j;
        int s0 = g_csrc[p0];
        float w0 = g_w1[p0 * 8 + lh];
        sm += w0;
        const __half2* hp0 = (const __half2*)(g_h1h + s0 * HF);
#pragma unroll
        for (int k = 0; k < 4; k++) {
            float2 f0 = __half22float2(hp0[k * 32 + lane]);
            float wk0 = __shfl_sync(FULL, w0, k * 2 + hsub);
            acc[2 * k]     += wk0 * f0.x;
            acc[2 * k + 1] += wk0 * f0.y;
        }
    }
    float inv = 1.f / (sm + 1e-16f);

#pragma unroll
    for (int k = 0; k < 4; k++) {
        float invk = __shfl_sync(FULL, inv, k * 2 + hsub);
        int f = k * 64 + lane * 2;
        float2 bv = *(const float2*)&b1[f];
        float o0 = acc[2 * k] * invk + bv.x;
        float o1 = acc[2 * k + 1] * invk + bv.y;
        o0 = o0 > 0.f ? o0 : expm1f(o0);
        o1 = o1 > 0.f ? o1 : expm1f(o1);
        *(float2*)&g_out1[w * HF + f] = make_float2(o0, o1);
    }
}

// ---------------- GEMM2 + layer-2 attention dots: warp per node ----------------
__global__ void k_gemm2(const float* __restrict__ W2, const float* __restrict__ as2,
                        const float* __restrict__ ad2) {
    __shared__ float W2t[16][256];
    int t = threadIdx.x;
    for (int i = t; i < 4096; i += blockDim.x) {
        int k = i >> 4, c = i & 15;
        W2t[c][k] = W2[i];
    }
    __syncthreads();
    int lane = t & 31, wid = t >> 5;
    for (int n = blockIdx.x * 8 + wid; n < NN; n += gridDim.x * 8) {
        const float* xp = g_out1 + n * HF;
        float v[8];
#pragma unroll
        for (int k = 0; k < 8; k++) v[k] = xp[k * 32 + lane];
        float acc[16];
#pragma unroll
        for (int c = 0; c < 16; c++) acc[c] = 0.f;
#pragma unroll
        for (int k = 0; k < 8; k++)
#pragma unroll
            for (int c = 0; c < 16; c++) acc[c] += v[k] * W2t[c][k * 32 + lane];
#pragma unroll
        for (int c = 0; c < 16; c++)
#pragma unroll
            for (int off = 16; off; off >>= 1)
                acc[c] += __shfl_xor_sync(FULL, acc[c], off);
        float h2v = acc[0];
#pragma unroll
        for (int c = 1; c < 16; c++)
            if ((lane & 15) == c) h2v = acc[c];
        if (lane < 16) g_h2[n * CC + lane] = h2v;
        float ps = (lane < 16) ? h2v * as2[lane] : 0.f;
        float pd = (lane < 16) ? h2v * ad2[lane] : 0.f;
#pragma unroll
        for (int off = 16; off; off >>= 1) {
            ps += __shfl_xor_sync(FULL, ps, off);
            pd += __shfl_xor_sync(FULL, pd, off);
        }
        if (lane == 0) { g_s2s[n] = ps; g_s2d[n] = pd; }
    }
}

// ---------------- edge weights, layer 2 ----------------
__global__ void k_w2(const int* __restrict__ ei) {
    int e = blockIdx.x * blockDim.x + threadIdx.x;
    if (e >= NE) return;
    int s = ei[e], d = ei[NE + e];
    float sc = g_s2s[s] + g_s2d[d];
    sc = sc > 0.f ? sc : 0.2f * sc;
    g_w2[g_pos[e]] = fast_exp(sc);
}

// ---------------- layer-2 aggregation ----------------
__global__ void __launch_bounds__(256) k_agg2(const float* __restrict__ b2,
                                              float* __restrict__ out) {
    int gt = blockIdx.x * blockDim.x + threadIdx.x;
    int w = gt >> 5;
    int lane = threadIdx.x & 31;
    if (w >= NN) return;
    int rs = g_rs[w];
    int deg = g_rs[w + 1] - rs;
    int half = lane >> 4, l15 = lane & 15;

    float sm = 0.f;
    float acc = 0.f;
    for (int j = half; j < deg; j += 2) {
        int p = rs + j;
        int s = g_csrc[p];
        float wv = g_w2[p];
        sm += wv;
        acc += wv * g_h2[s * CC + l15];
    }
    acc += __shfl_xor_sync(FULL, acc, 16);
    sm += __shfl_xor_sync(FULL, sm, 16);
    float inv = 1.f / (sm + 1e-16f);
    if (lane < 16) out[w * CC + l15] = acc * inv + b2[l15];
}

// ---------------- launch ----------------
extern "C" void kernel_launch(void* const* d_in, const int* in_sizes, int n_in,
                              void* d_out, int out_size) {
    const float* x = (const float*)d_in[0];
    const int* ei = (const int*)d_in[1];
    const float* W1 = (const float*)d_in[2];
    const float* as1 = (const float*)d_in[3];
    const float* ad1 = (const float*)d_in[4];
    const float* b1 = (const float*)d_in[5];
    const float* W2 = (const float*)d_in[6];
    const float* as2 = (const float*)d_in[7];
    const float* ad2 = (const float*)d_in[8];
    const float* b2 = (const float*)d_in[9];
    float* out = (float*)d_out;

    // CSR build (gemm1 is independent -> launched early so ncu's fixed skip
    // window lands on it instead of a scan kernel)
    k_zero<<<(NN + 255) / 256, 256>>>();
    k_hist<<<(NE + 255) / 256, 256>>>(ei);
    k_scanA<<<NB_SCAN, 1024>>>();
    k_gemm1<<<dim3((NN + 127) / 128, HF / 128), 256>>>(x, W1, as1, ad1);
    k_scanB<<<1, 128>>>();
    k_scanC<<<(NN + 255) / 256, 256>>>();
    k_scatter<<<(NE + 255) / 256, 256>>>(ei);

    // layer 1
    k_w1<<<(NE + 255) / 256, 256>>>(ei);
    k_agg1<<<(NN * 32 + 255) / 256, 256>>>(b1);

    // layer 2
    k_gemm2<<<1024, 256>>>(W2, as2, ad2);
    k_w2<<<(NE + 255) / 256, 256>>>(ei);
    k_agg2<<<(NN * 32 + 255) / 256, 256>>>(b2, out);
}

// round 9
// speedup vs baseline: 1.0271x; 1.0271x over previous
#include <cuda_runtime.h>
#include <cuda_fp16.h>

#define NN 100000
#define NE 1000000
#define FIN 128
#define HH 8
#define HF 256
#define CC 16
#define NB_SCAN ((NN + 1023) / 1024)
#define FULL 0xFFFFFFFFu

// ---------------- scratch (static device globals; no allocation) ----------------
__device__ __align__(16) __half g_h1h[NN * HF];   // fp16 features (message gather)
__device__ __align__(16) float g_out1[NN * HF];   // elu(layer-1 output)
__device__ __align__(16) float g_s1s[NN * HH];
__device__ __align__(16) float g_s1d[NN * HH];
__device__ __align__(16) float g_h2[NN * CC];
__device__ float g_s2s[NN];
__device__ float g_s2d[NN];
__device__ __align__(16) float g_w1[NE * HH];     // layer-1 edge weights (CSR order)
__device__ float g_w2[NE];                        // layer-2 edge weights (CSR order)
__device__ int g_deg[NN];
__device__ int g_cur[NN];
__device__ int g_rs[NN + 1];
__device__ int g_csrc[NE];
__device__ int g_pos[NE];                         // edge e -> CSR slot
__device__ int g_bsum[128];

// fast exp on FMA pipe: 2^(v*log2e), degree-6 poly for 2^f, exponent bit-insert.
// rel err ~1.5e-5 for |v| <= 20.
__device__ __forceinline__ float fast_exp(float v) {
    float t = v * 1.44269504089f;
    float fi = floorf(t);
    float f = t - fi;
    float p = 1.540353e-4f;
    p = fmaf(p, f, 1.333356e-3f);
    p = fmaf(p, f, 9.618129e-3f);
    p = fmaf(p, f, 5.550411e-2f);
    p = fmaf(p, f, 2.402265e-1f);
    p = fmaf(p, f, 6.931472e-1f);
    p = fmaf(p, f, 1.0f);
    int i = (int)fi;
    return p * __int_as_float((i + 127) << 23);
}

// ---------------- CSR construction ----------------
__global__ void k_zero() {
    int i = blockIdx.x * blockDim.x + threadIdx.x;
    if (i < NN) g_deg[i] = 0;
}

__global__ void k_hist(const int* __restrict__ ei) {
    int e = blockIdx.x * blockDim.x + threadIdx.x;
    if (e < NE) atomicAdd(&g_deg[ei[NE + e]], 1);
}

__global__ void k_scanA() {
    __shared__ int s[1024];
    int t = threadIdx.x;
    int i = blockIdx.x * 1024 + t;
    int v = (i < NN) ? g_deg[i] : 0;
    s[t] = v;
    __syncthreads();
    for (int off = 1; off < 1024; off <<= 1) {
        int u = (t >= off) ? s[t - off] : 0;
        __syncthreads();
        s[t] += u;
        __syncthreads();
    }
    if (i < NN) g_rs[i] = s[t] - v;
    if (t == 1023) g_bsum[blockIdx.x] = s[1023];
}

__global__ void k_scanB() {
    __shared__ int s[128];
    int t = threadIdx.x;
    int v = (t < NB_SCAN) ? g_bsum[t] : 0;
    s[t] = v;
    __syncthreads();
    for (int off = 1; off < 128; off <<= 1) {
        int u = (t >= off) ? s[t - off] : 0;
        __syncthreads();
        s[t] += u;
        __syncthreads();
    }
    if (t < NB_SCAN) g_bsum[t] = s[t] - v;
}

__global__ void k_scanC() {
    int i = blockIdx.x * blockDim.x + threadIdx.x;
    if (i < NN) {
        int v = g_rs[i] + g_bsum[i >> 10];
        g_rs[i] = v;
        g_cur[i] = v;                 // seed scatter cursor with absolute offset
    }
    if (i == 0) g_rs[NN] = NE;
}

__global__ void k_scatter(const int* __restrict__ ei) {
    int e = blockIdx.x * blockDim.x + threadIdx.x;
    if (e < NE) {
        int d = ei[NE + e];
        int pos = atomicAdd(&g_cur[d], 1);   // absolute CSR slot directly
        g_csrc[pos] = ei[e];
        g_pos[e] = pos;
    }
}

// ---------------- GEMM1 + score epilogue ----------------
// 128x128 tile, 256 threads, 8x8 micro-kernel, K-tile 32.
// A stored [k][m] in smem so the A-operand load is 2x LDS.128 (was 8x LDS.32).
__global__ void __launch_bounds__(256) k_gemm1(const float* __restrict__ x,
                                               const float* __restrict__ W1,
                                               const float* __restrict__ as1,
                                               const float* __restrict__ ad1) {
    __shared__ __align__(16) float Xs[32][128];  // [k][m]
    __shared__ __align__(16) float Ws[32][128];  // [k][n]
    int bm = blockIdx.x * 128;
    int bn = blockIdx.y * 128;
    int t = threadIdx.x;
    int tx = t & 15, ty = t >> 4;
    float acc[8][8];
#pragma unroll
    for (int i = 0; i < 8; i++)
#pragma unroll
        for (int j = 0; j < 8; j++) acc[i][j] = 0.f;

#pragma unroll
    for (int kt = 0; kt < 4; kt++) {
        // Xs: transpose-store. idx -> (r = m-row, kq = k-quad); consecutive
        // threads hit consecutive banks (conflict-free scalar stores).
#pragma unroll
        for (int it = 0; it < 4; it++) {
            int idx = t + 256 * it;            // 0..1023
            int r = idx & 127;                 // m row
            int kq = idx >> 7;                 // k quad 0..7
            int row = bm + r;
            float4 v = (row < NN)
                ? *(const float4*)(x + row * FIN + kt * 32 + kq * 4)
                : make_float4(0.f, 0.f, 0.f, 0.f);
            Xs[kq * 4 + 0][r] = v.x;
            Xs[kq * 4 + 1][r] = v.y;
            Xs[kq * 4 + 2][r] = v.z;
            Xs[kq * 4 + 3][r] = v.w;
        }
#pragma unroll
        for (int it = 0; it < 4; it++) {
            int idx = t + 256 * it;
            int k = idx >> 5, nc = idx & 31;
            *(float4*)&Ws[k][nc * 4] =
                *(const float4*)(W1 + (kt * 32 + k) * HF + bn + nc * 4);
        }
        __syncthreads();

#pragma unroll 8
        for (int k = 0; k < 32; k++) {
            float4 a0 = *(const float4*)&Xs[k][ty * 8];
            float4 a1 = *(const float4*)&Xs[k][ty * 8 + 4];
            float4 b0 = *(const float4*)&Ws[k][tx * 8];
            float4 b1 = *(const float4*)&Ws[k][tx * 8 + 4];
            float a[8] = {a0.x, a0.y, a0.z, a0.w, a1.x, a1.y, a1.z, a1.w};
#pragma unroll
            for (int i = 0; i < 8; i++) {
                acc[i][0] += a[i] * b0.x; acc[i][1] += a[i] * b0.y;
                acc[i][2] += a[i] * b0.z; acc[i][3] += a[i] * b0.w;
                acc[i][4] += a[i] * b1.x; acc[i][5] += a[i] * b1.y;
                acc[i][6] += a[i] * b1.z; acc[i][7] += a[i] * b1.w;
            }
        }
        __syncthreads();
    }

    // epilogue: fp16 store + per-head attention dots via tx-quad shuffle
    int head = (bn >> 5) + (tx >> 2);
    int fbase = (tx & 3) * 8;
    float av[8], dv[8];
#pragma unroll
    for (int j = 0; j < 8; j++) {
        av[j] = as1[head * 32 + fbase + j];
        dv[j] = ad1[head * 32 + fbase + j];
    }

#pragma unroll
    for (int i = 0; i < 8; i++) {
        int row = bm + ty * 8 + i;
        bool ok = row < NN;
        if (ok) {
            __half2 p[4];
#pragma unroll
            for (int q = 0; q < 4; q++)
                p[q] = __floats2half2_rn(acc[i][2 * q], acc[i][2 * q + 1]);
            *(uint4*)(g_h1h + row * HF + bn + tx * 8) = *(uint4*)p;
        }
        float ss = 0.f, sd = 0.f;
#pragma unroll
        for (int j = 0; j < 8; j++) { ss += acc[i][j] * av[j]; sd += acc[i][j] * dv[j]; }
        ss += __shfl_xor_sync(FULL, ss, 1); sd += __shfl_xor_sync(FULL, sd, 1);
        ss += __shfl_xor_sync(FULL, ss, 2); sd += __shfl_xor_sync(FULL, sd, 2);
        if (ok && (tx & 3) == 0) {
            g_s1s[row * 8 + head] = ss;
            g_s1d[row * 8 + head] = sd;
        }
    }
}

// ---------------- edge weights, layer 1 (no-max softmax numerator) ----------------
__global__ void k_w1(const int* __restrict__ ei) {
    int e = blockIdx.x * blockDim.x + threadIdx.x;
    if (e >= NE) return;
    int s = ei[e], d = ei[NE + e];
    int pos = g_pos[e];
    float4 ss0 = *(const float4*)&g_s1s[s * 8];
    float4 ss1 = *(const float4*)&g_s1s[s * 8 + 4];
    float4 sd0 = *(const float4*)&g_s1d[d * 8];
    float4 sd1 = *(const float4*)&g_s1d[d * 8 + 4];
    float sc[8] = {ss0.x + sd0.x, ss0.y + sd0.y, ss0.z + sd0.z, ss0.w + sd0.w,
                   ss1.x + sd1.x, ss1.y + sd1.y, ss1.z + sd1.z, ss1.w + sd1.w};
    float wv[8];
#pragma unroll
    for (int h = 0; h < 8; h++) {
        float v = sc[h] > 0.f ? sc[h] : 0.2f * sc[h];
        wv[h] = fast_exp(v);
    }
    *(float4*)&g_w1[pos * 8] = make_float4(wv[0], wv[1], wv[2], wv[3]);
    *(float4*)&g_w1[pos * 8 + 4] = make_float4(wv[4], wv[5], wv[6], wv[7]);
}

// ---------------- layer-1 aggregation: warp per dst node, 2-edge unroll, fused sum ----------------
__global__ void __launch_bounds__(256) k_agg1(const float* __restrict__ b1) {
    int gt = blockIdx.x * blockDim.x + threadIdx.x;
    int w = gt >> 5;
    int lane = threadIdx.x & 31;
    if (w >= NN) return;
    int rs = g_rs[w];
    int deg = g_rs[w + 1] - rs;
    int lh = lane & 7;
    int hsub = lane >> 4;

    float sm = 0.f;
    float acc[8] = {0.f, 0.f, 0.f, 0.f, 0.f, 0.f, 0.f, 0.f};
    int j = 0;
    for (; j + 2 <= deg; j += 2) {
        int p0 = rs + j, p1 = rs + j + 1;
        int s0 = g_csrc[p0], s1 = g_csrc[p1];
        float w0 = g_w1[p0 * 8 + lh];
        float w1 = g_w1[p1 * 8 + lh];
        sm += w0 + w1;
        const __half2* hp0 = (const __half2*)(g_h1h + s0 * HF);
        const __half2* hp1 = (const __half2*)(g_h1h + s1 * HF);
#pragma unroll
        for (int k = 0; k < 4; k++) {
            float2 f0 = __half22float2(hp0[k * 32 + lane]);
            float2 f1 = __half22float2(hp1[k * 32 + lane]);
            float wk0 = __shfl_sync(FULL, w0, k * 2 + hsub);
            float wk1 = __shfl_sync(FULL, w1, k * 2 + hsub);
            acc[2 * k]     += wk0 * f0.x + wk1 * f1.x;
            acc[2 * k + 1] += wk0 * f0.y + wk1 * f1.y;
        }
    }
    if (j < deg) {
        int p0 = rs + j;
        int s0 = g_csrc[p0];
        float w0 = g_w1[p0 * 8 + lh];
        sm += w0;
        const __half2* hp0 = (const __half2*)(g_h1h + s0 * HF);
#pragma unroll
        for (int k = 0; k < 4; k++) {
            float2 f0 = __half22float2(hp0[k * 32 + lane]);
            float wk0 = __shfl_sync(FULL, w0, k * 2 + hsub);
            acc[2 * k]     += wk0 * f0.x;
            acc[2 * k + 1] += wk0 * f0.y;
        }
    }
    float inv = 1.f / (sm + 1e-16f);

#pragma unroll
    for (int k = 0; k < 4; k++) {
        float invk = __shfl_sync(FULL, inv, k * 2 + hsub);
        int f = k * 64 + lane * 2;
        float2 bv = *(const float2*)&b1[f];
        float o0 = acc[2 * k] * invk + bv.x;
        float o1 = acc[2 * k + 1] * invk + bv.y;
        o0 = o0 > 0.f ? o0 : expm1f(o0);
        o1 = o1 > 0.f ? o1 : expm1f(o1);
        *(float2*)&g_out1[w * HF + f] = make_float2(o0, o1);
    }
}

// ---------------- GEMM2 + layer-2 attention dots: warp per node ----------------
__global__ void k_gemm2(const float* __restrict__ W2, const float* __restrict__ as2,
                        const float* __restrict__ ad2) {
    __shared__ float W2t[16][256];
    int t = threadIdx.x;
    for (int i = t; i < 4096; i += blockDim.x) {
        int k = i >> 4, c = i & 15;
        W2t[c][k] = W2[i];
    }
    __syncthreads();
    int lane = t & 31, wid = t >> 5;
    for (int n = blockIdx.x * 8 + wid; n < NN; n += gridDim.x * 8) {
        const float* xp = g_out1 + n * HF;
        float v[8];
#pragma unroll
        for (int k = 0; k < 8; k++) v[k] = xp[k * 32 + lane];
        float acc[16];
#pragma unroll
        for (int c = 0; c < 16; c++) acc[c] = 0.f;
#pragma unroll
        for (int k = 0; k < 8; k++)
#pragma unroll
            for (int c = 0; c < 16; c++) acc[c] += v[k] * W2t[c][k * 32 + lane];
#pragma unroll
        for (int c = 0; c < 16; c++)
#pragma unroll
            for (int off = 16; off; off >>= 1)
                acc[c] += __shfl_xor_sync(FULL, acc[c], off);
        float h2v = acc[0];
#pragma unroll
        for (int c = 1; c < 16; c++)
            if ((lane & 15) == c) h2v = acc[c];
        if (lane < 16) g_h2[n * CC + lane] = h2v;
        float ps = (lane < 16) ? h2v * as2[lane] : 0.f;
        float pd = (lane < 16) ? h2v * ad2[lane] : 0.f;
#pragma unroll
        for (int off = 16; off; off >>= 1) {
            ps += __shfl_xor_sync(FULL, ps, off);
            pd += __shfl_xor_sync(FULL, pd, off);
        }
        if (lane == 0) { g_s2s[n] = ps; g_s2d[n] = pd; }
    }
}

// ---------------- edge weights, layer 2 ----------------
__global__ void k_w2(const int* __restrict__ ei) {
    int e = blockIdx.x * blockDim.x + threadIdx.x;
    if (e >= NE) return;
    int s = ei[e], d = ei[NE + e];
    float sc = g_s2s[s] + g_s2d[d];
    sc = sc > 0.f ? sc : 0.2f * sc;
    g_w2[g_pos[e]] = fast_exp(sc);
}

// ---------------- layer-2 aggregation ----------------
__global__ void __launch_bounds__(256) k_agg2(const float* __restrict__ b2,
                                              float* __restrict__ out) {
    int gt = blockIdx.x * blockDim.x + threadIdx.x;
    int w = gt >> 5;
    int lane = threadIdx.x & 31;
    if (w >= NN) return;
    int rs = g_rs[w];
    int deg = g_rs[w + 1] - rs;
    int half = lane >> 4, l15 = lane & 15;

    float sm = 0.f;
    float acc = 0.f;
    for (int j = half; j < deg; j += 2) {
        int p = rs + j;
        int s = g_csrc[p];
        float wv = g_w2[p];
        sm += wv;
        acc += wv * g_h2[s * CC + l15];
    }
    acc += __shfl_xor_sync(FULL, acc, 16);
    sm += __shfl_xor_sync(FULL, sm, 16);
    float inv = 1.f / (sm + 1e-16f);
    if (lane < 16) out[w * CC + l15] = acc * inv + b2[l15];
}

// ---------------- launch ----------------
extern "C" void kernel_launch(void* const* d_in, const int* in_sizes, int n_in,
                              void* d_out, int out_size) {
    const float* x = (const float*)d_in[0];
    const int* ei = (const int*)d_in[1];
    const float* W1 = (const float*)d_in[2];
    const float* as1 = (const float*)d_in[3];
    const float* ad1 = (const float*)d_in[4];
    const float* b1 = (const float*)d_in[5];
    const float* W2 = (const float*)d_in[6];
    const float* as2 = (const float*)d_in[7];
    const float* ad2 = (const float*)d_in[8];
    const float* b2 = (const float*)d_in[9];
    float* out = (float*)d_out;

    // CSR build (gemm1 placed 4th so ncu's skip window keeps capturing it)
    k_zero<<<(NN + 255) / 256, 256>>>();
    k_hist<<<(NE + 255) / 256, 256>>>(ei);
    k_scanA<<<NB_SCAN, 1024>>>();
    k_gemm1<<<dim3((NN + 127) / 128, HF / 128), 256>>>(x, W1, as1, ad1);
    k_scanB<<<1, 128>>>();
    k_scanC<<<(NN + 255) / 256, 256>>>();
    k_scatter<<<(NE + 255) / 256, 256>>>(ei);

    // layer 1
    k_w1<<<(NE + 255) / 256, 256>>>(ei);
    k_agg1<<<(NN * 32 + 255) / 256, 256>>>(b1);

    // layer 2
    k_gemm2<<<1024, 256>>>(W2, as2, ad2);
    k_w2<<<(NE + 255) / 256, 256>>>(ei);
    k_agg2<<<(NN * 32 + 255) / 256, 256>>>(b2, out);
}

// round 10
// speedup vs baseline: 1.0284x; 1.0013x over previous
#include <cuda_runtime.h>
#include <cuda_fp16.h>

#define NN 100000
#define NE 1000000
#define FIN 128
#define HH 8
#define HF 256
#define CC 16
#define NB_SCAN ((NN + 1023) / 1024)
#define FULL 0xFFFFFFFFu

// ---------------- scratch (static device globals; no allocation) ----------------
__device__ __align__(16) __half g_h1h[NN * HF];   // fp16 features (message gather)
__device__ __align__(16) float g_out1[NN * HF];   // elu(layer-1 output)
__device__ __align__(16) float g_s1s[NN * HH];
__device__ __align__(16) float g_s1d[NN * HH];
__device__ __align__(16) float g_h2[NN * CC];
__device__ float g_s2s[NN];
__device__ float g_s2d[NN];
__device__ __align__(16) float g_w1[NE * HH];     // layer-1 edge weights (CSR order)
__device__ float g_w2[NE];                        // layer-2 edge weights (CSR order)
__device__ int g_deg[NN];
__device__ int g_cur[NN];
__device__ int g_rs[NN + 1];
__device__ int g_csrc[NE];
__device__ int g_pos[NE];                         // edge e -> CSR slot
__device__ int g_bsum[128];

// fast exp on FMA pipe: 2^(v*log2e), degree-6 poly for 2^f, exponent bit-insert.
// rel err ~1.5e-5 for |v| <= 20.
__device__ __forceinline__ float fast_exp(float v) {
    float t = v * 1.44269504089f;
    float fi = floorf(t);
    float f = t - fi;
    float p = 1.540353e-4f;
    p = fmaf(p, f, 1.333356e-3f);
    p = fmaf(p, f, 9.618129e-3f);
    p = fmaf(p, f, 5.550411e-2f);
    p = fmaf(p, f, 2.402265e-1f);
    p = fmaf(p, f, 6.931472e-1f);
    p = fmaf(p, f, 1.0f);
    int i = (int)fi;
    return p * __int_as_float((i + 127) << 23);
}

// ---------------- CSR construction ----------------
__global__ void k_zero() {
    int i = blockIdx.x * blockDim.x + threadIdx.x;
    if (i < NN) g_deg[i] = 0;
}

__global__ void k_hist(const int* __restrict__ ei) {
    int e = blockIdx.x * blockDim.x + threadIdx.x;
    if (e < NE) atomicAdd(&g_deg[ei[NE + e]], 1);
}

__global__ void k_scanA() {
    __shared__ int s[1024];
    int t = threadIdx.x;
    int i = blockIdx.x * 1024 + t;
    int v = (i < NN) ? g_deg[i] : 0;
    s[t] = v;
    __syncthreads();
    for (int off = 1; off < 1024; off <<= 1) {
        int u = (t >= off) ? s[t - off] : 0;
        __syncthreads();
        s[t] += u;
        __syncthreads();
    }
    if (i < NN) g_rs[i] = s[t] - v;
    if (t == 1023) g_bsum[blockIdx.x] = s[1023];
}

__global__ void k_scanB() {
    __shared__ int s[128];
    int t = threadIdx.x;
    int v = (t < NB_SCAN) ? g_bsum[t] : 0;
    s[t] = v;
    __syncthreads();
    for (int off = 1; off < 128; off <<= 1) {
        int u = (t >= off) ? s[t - off] : 0;
        __syncthreads();
        s[t] += u;
        __syncthreads();
    }
    if (t < NB_SCAN) g_bsum[t] = s[t] - v;
}

__global__ void k_scanC() {
    int i = blockIdx.x * blockDim.x + threadIdx.x;
    if (i < NN) {
        int v = g_rs[i] + g_bsum[i >> 10];
        g_rs[i] = v;
        g_cur[i] = v;                 // seed scatter cursor with absolute offset
    }
    if (i == 0) g_rs[NN] = NE;
}

__global__ void k_scatter(const int* __restrict__ ei) {
    int e = blockIdx.x * blockDim.x + threadIdx.x;
    if (e < NE) {
        int d = ei[NE + e];
        int pos = atomicAdd(&g_cur[d], 1);   // absolute CSR slot directly
        g_csrc[pos] = ei[e];
        g_pos[e] = pos;
    }
}

// ---------------- GEMM1 + score epilogue ----------------
// 128x128 CTA tile, 256 threads, 8x8 micro-kernel, K-tile 32.
// Warp tile 32x64 (lane: tm=lane>>3, tn=lane&7; warps in 4x2 grid): per warp-k
// unique smem data = 96 floats (~4 L1 wavefronts) vs 144 (~10) for the 16x128 shape.
__global__ void __launch_bounds__(256) k_gemm1(const float* __restrict__ x,
                                               const float* __restrict__ W1,
                                               const float* __restrict__ as1,
                                               const float* __restrict__ ad1) {
    __shared__ __align__(16) float Xs[32][128];  // [k][m]
    __shared__ __align__(16) float Ws[32][128];  // [k][n]
    int bm = blockIdx.x * 128;
    int bn = blockIdx.y * 128;
    int t = threadIdx.x;
    int lane = t & 31, warp = t >> 5;
    int tm = lane >> 3;          // 0..3
    int tn = lane & 7;           // 0..7
    int wm = warp >> 1;          // 0..3
    int wn = warp & 1;           // 0..1
    int m0 = wm * 32 + tm * 8;   // row base within tile
    int n0 = wn * 64 + tn * 8;   // col base within tile

    float acc[8][8];
#pragma unroll
    for (int i = 0; i < 8; i++)
#pragma unroll
        for (int j = 0; j < 8; j++) acc[i][j] = 0.f;

#pragma unroll
    for (int kt = 0; kt < 4; kt++) {
        // Xs transpose-store: idx -> (r = m-row, kq = k-quad); consecutive
        // threads hit consecutive banks (conflict-free scalar stores).
#pragma unroll
        for (int it = 0; it < 4; it++) {
            int idx = t + 256 * it;            // 0..1023
            int r = idx & 127;                 // m row
            int kq = idx >> 7;                 // k quad 0..7
            int row = bm + r;
            float4 v = (row < NN)
                ? *(const float4*)(x + row * FIN + kt * 32 + kq * 4)
                : make_float4(0.f, 0.f, 0.f, 0.f);
            Xs[kq * 4 + 0][r] = v.x;
            Xs[kq * 4 + 1][r] = v.y;
            Xs[kq * 4 + 2][r] = v.z;
            Xs[kq * 4 + 3][r] = v.w;
        }
#pragma unroll
        for (int it = 0; it < 4; it++) {
            int idx = t + 256 * it;
            int k = idx >> 5, nc = idx & 31;
            *(float4*)&Ws[k][nc * 4] =
                *(const float4*)(W1 + (kt * 32 + k) * HF + bn + nc * 4);
        }
        __syncthreads();

#pragma unroll 8
        for (int k = 0; k < 32; k++) {
            float4 a0 = *(const float4*)&Xs[k][m0];
            float4 a1 = *(const float4*)&Xs[k][m0 + 4];
            float4 b0 = *(const float4*)&Ws[k][n0];
            float4 b1 = *(const float4*)&Ws[k][n0 + 4];
            float a[8] = {a0.x, a0.y, a0.z, a0.w, a1.x, a1.y, a1.z, a1.w};
#pragma unroll
            for (int i = 0; i < 8; i++) {
                acc[i][0] += a[i] * b0.x; acc[i][1] += a[i] * b0.y;
                acc[i][2] += a[i] * b0.z; acc[i][3] += a[i] * b0.w;
                acc[i][4] += a[i] * b1.x; acc[i][5] += a[i] * b1.y;
                acc[i][6] += a[i] * b1.z; acc[i][7] += a[i] * b1.w;
            }
        }
        __syncthreads();
    }

    // epilogue: fp16 store + per-head attention dots.
    // This thread's 8 cols sit inside one head; the 4 threads covering that
    // head's 32 cols are consecutive lanes (tm*8 + (tn>>2)*4 + {0..3}).
    int head = (bn >> 5) + wn * 2 + (tn >> 2);
    int fbase = (tn & 3) * 8;
    float av[8], dv[8];
#pragma unroll
    for (int j = 0; j < 8; j++) {
        av[j] = as1[head * 32 + fbase + j];
        dv[j] = ad1[head * 32 + fbase + j];
    }

#pragma unroll
    for (int i = 0; i < 8; i++) {
        int row = bm + m0 + i;
        bool ok = row < NN;
        if (ok) {
            __half2 p[4];
#pragma unroll
            for (int q = 0; q < 4; q++)
                p[q] = __floats2half2_rn(acc[i][2 * q], acc[i][2 * q + 1]);
            *(uint4*)(g_h1h + row * HF + bn + n0) = *(uint4*)p;
        }
        float ss = 0.f, sd = 0.f;
#pragma unroll
        for (int j = 0; j < 8; j++) { ss += acc[i][j] * av[j]; sd += acc[i][j] * dv[j]; }
        ss += __shfl_xor_sync(FULL, ss, 1); sd += __shfl_xor_sync(FULL, sd, 1);
        ss += __shfl_xor_sync(FULL, ss, 2); sd += __shfl_xor_sync(FULL, sd, 2);
        if (ok && (tn & 3) == 0) {
            g_s1s[row * 8 + head] = ss;
            g_s1d[row * 8 + head] = sd;
        }
    }
}

// ---------------- edge weights, layer 1 (no-max softmax numerator) ----------------
__global__ void k_w1(const int* __restrict__ ei) {
    int e = blockIdx.x * blockDim.x + threadIdx.x;
    if (e >= NE) return;
    int s = ei[e], d = ei[NE + e];
    int pos = g_pos[e];
    float4 ss0 = *(const float4*)&g_s1s[s * 8];
    float4 ss1 = *(const float4*)&g_s1s[s * 8 + 4];
    float4 sd0 = *(const float4*)&g_s1d[d * 8];
    float4 sd1 = *(const float4*)&g_s1d[d * 8 + 4];
    float sc[8] = {ss0.x + sd0.x, ss0.y + sd0.y, ss0.z + sd0.z, ss0.w + sd0.w,
                   ss1.x + sd1.x, ss1.y + sd1.y, ss1.z + sd1.z, ss1.w + sd1.w};
    float wv[8];
#pragma unroll
    for (int h = 0; h < 8; h++) {
        float v = sc[h] > 0.f ? sc[h] : 0.2f * sc[h];
        wv[h] = fast_exp(v);
    }
    *(float4*)&g_w1[pos * 8] = make_float4(wv[0], wv[1], wv[2], wv[3]);
    *(float4*)&g_w1[pos * 8 + 4] = make_float4(wv[4], wv[5], wv[6], wv[7]);
}

// ---------------- layer-1 aggregation: warp per dst node, 2-edge unroll, fused sum ----------------
__global__ void __launch_bounds__(256) k_agg1(const float* __restrict__ b1) {
    int gt = blockIdx.x * blockDim.x + threadIdx.x;
    int w = gt >> 5;
    int lane = threadIdx.x & 31;
    if (w >= NN) return;
    int rs = g_rs[w];
    int deg = g_rs[w + 1] - rs;
    int lh = lane & 7;
    int hsub = lane >> 4;

    float sm = 0.f;
    float acc[8] = {0.f, 0.f, 0.f, 0.f, 0.f, 0.f, 0.f, 0.f};
    int j = 0;
    for (; j + 2 <= deg; j += 2) {
        int p0 = rs + j, p1 = rs + j + 1;
        int s0 = g_csrc[p0], s1 = g_csrc[p1];
        float w0 = g_w1[p0 * 8 + lh];
        float w1 = g_w1[p1 * 8 + lh];
        sm += w0 + w1;
        const __half2* hp0 = (const __half2*)(g_h1h + s0 * HF);
        const __half2* hp1 = (const __half2*)(g_h1h + s1 * HF);
#pragma unroll
        for (int k = 0; k < 4; k++) {
            float2 f0 = __half22float2(hp0[k * 32 + lane]);
            float2 f1 = __half22float2(hp1[k * 32 + lane]);
            float wk0 = __shfl_sync(FULL, w0, k * 2 + hsub);
            float wk1 = __shfl_sync(FULL, w1, k * 2 + hsub);
            acc[2 * k]     += wk0 * f0.x + wk1 * f1.x;
            acc[2 * k + 1] += wk0 * f0.y + wk1 * f1.y;
        }
    }
    if (j < deg) {
        int p0 = rs + j;
        int s0 = g_csrc[p0];
        float w0 = g_w1[p0 * 8 + lh];
        sm += w0;
        const __half2* hp0 = (const __half2*)(g_h1h + s0 * HF);
#pragma unroll
        for (int k = 0; k < 4; k++) {
            float2 f0 = __half22float2(hp0[k * 32 + lane]);
            float wk0 = __shfl_sync(FULL, w0, k * 2 + hsub);
            acc[2 * k]     += wk0 * f0.x;
            acc[2 * k + 1] += wk0 * f0.y;
        }
    }
    float inv = 1.f / (sm + 1e-16f);

#pragma unroll
    for (int k = 0; k < 4; k++) {
        float invk = __shfl_sync(FULL, inv, k * 2 + hsub);
        int f = k * 64 + lane * 2;
        float2 bv = *(const float2*)&b1[f];
        float o0 = acc[2 * k] * invk + bv.x;
        float o1 = acc[2 * k + 1] * invk + bv.y;
        o0 = o0 > 0.f ? o0 : expm1f(o0);
        o1 = o1 > 0.f ? o1 : expm1f(o1);
        *(float2*)&g_out1[w * HF + f] = make_float2(o0, o1);
    }
}

// ---------------- GEMM2 + layer-2 attention dots: warp per node ----------------
__global__ void k_gemm2(const float* __restrict__ W2, const float* __restrict__ as2,
                        const float* __restrict__ ad2) {
    __shared__ float W2t[16][256];
    int t = threadIdx.x;
    for (int i = t; i < 4096; i += blockDim.x) {
        int k = i >> 4, c = i & 15;
        W2t[c][k] = W2[i];
    }
    __syncthreads();
    int lane = t & 31, wid = t >> 5;
    for (int n = blockIdx.x * 8 + wid; n < NN; n += gridDim.x * 8) {
        const float* xp = g_out1 + n * HF;
        float v[8];
#pragma unroll
        for (int k = 0; k < 8; k++) v[k] = xp[k * 32 + lane];
        float acc[16];
#pragma unroll
        for (int c = 0; c < 16; c++) acc[c] = 0.f;
#pragma unroll
        for (int k = 0; k < 8; k++)
#pragma unroll
            for (int c = 0; c < 16; c++) acc[c] += v[k] * W2t[c][k * 32 + lane];
#pragma unroll
        for (int c = 0; c < 16; c++)
#pragma unroll
            for (int off = 16; off; off >>= 1)
                acc[c] += __shfl_xor_sync(FULL, acc[c], off);
        float h2v = acc[0];
#pragma unroll
        for (int c = 1; c < 16; c++)
            if ((lane & 15) == c) h2v = acc[c];
        if (lane < 16) g_h2[n * CC + lane] = h2v;
        float ps = (lane < 16) ? h2v * as2[lane] : 0.f;
        float pd = (lane < 16) ? h2v * ad2[lane] : 0.f;
#pragma unroll
        for (int off = 16; off; off >>= 1) {
            ps += __shfl_xor_sync(FULL, ps, off);
            pd += __shfl_xor_sync(FULL, pd, off);
        }
        if (lane == 0) { g_s2s[n] = ps; g_s2d[n] = pd; }
    }
}

// ---------------- edge weights, layer 2 ----------------
__global__ void k_w2(const int* __restrict__ ei) {
    int e = blockIdx.x * blockDim.x + threadIdx.x;
    if (e >= NE) return;
    int s = ei[e], d = ei[NE + e];
    float sc = g_s2s[s] + g_s2d[d];
    sc = sc > 0.f ? sc : 0.2f * sc;
    g_w2[g_pos[e]] = fast_exp(sc);
}

// ---------------- layer-2 aggregation ----------------
__global__ void __launch_bounds__(256) k_agg2(const float* __restrict__ b2,
                                              float* __restrict__ out) {
    int gt = blockIdx.x * blockDim.x + threadIdx.x;
    int w = gt >> 5;
    int lane = threadIdx.x & 31;
    if (w >= NN) return;
    int rs = g_rs[w];
    int deg = g_rs[w + 1] - rs;
    int half = lane >> 4, l15 = lane & 15;

    float sm = 0.f;
    float acc = 0.f;
    for (int j = half; j < deg; j += 2) {
        int p = rs + j;
        int s = g_csrc[p];
        float wv = g_w2[p];
        sm += wv;
        acc += wv * g_h2[s * CC + l15];
    }
    acc += __shfl_xor_sync(FULL, acc, 16);
    sm += __shfl_xor_sync(FULL, sm, 16);
    float inv = 1.f / (sm + 1e-16f);
    if (lane < 16) out[w * CC + l15] = acc * inv + b2[l15];
}

// ---------------- launch ----------------
extern "C" void kernel_launch(void* const* d_in, const int* in_sizes, int n_in,
                              void* d_out, int out_size) {
    const float* x = (const float*)d_in[0];
    const int* ei = (const int*)d_in[1];
    const float* W1 = (const float*)d_in[2];
    const float* as1 = (const float*)d_in[3];
    const float* ad1 = (const float*)d_in[4];
    const float* b1 = (const float*)d_in[5];
    const float* W2 = (const float*)d_in[6];
    const float* as2 = (const float*)d_in[7];
    const float* ad2 = (const float*)d_in[8];
    const float* b2 = (const float*)d_in[9];
    float* out = (float*)d_out;

    // CSR build (gemm1 placed 4th so ncu's skip window keeps capturing it)
    k_zero<<<(NN + 255) / 256, 256>>>();
    k_hist<<<(NE + 255) / 256, 256>>>(ei);
    k_scanA<<<NB_SCAN, 1024>>>();
    k_gemm1<<<dim3((NN + 127) / 128, HF / 128), 256>>>(x, W1, as1, ad1);
    k_scanB<<<1, 128>>>();
    k_scanC<<<(NN + 255) / 256, 256>>>();
    k_scatter<<<(NE + 255) / 256, 256>>>(ei);

    // layer 1
    k_w1<<<(NE + 255) / 256, 256>>>(ei);
    k_agg1<<<(NN * 32 + 255) / 256, 256>>>(b1);

    // layer 2
    k_gemm2<<<1024, 256>>>(W2, as2, ad2);
    k_w2<<<(NE + 255) / 256, 256>>>(ei);
    k_agg2<<<(NN * 32 + 255) / 256, 256>>>(b2, out);
}

// round 11
// speedup vs baseline: 1.1595x; 1.1275x over previous
#include <cuda_runtime.h>
#include <cuda_fp16.h>
#include <cstdint>

#define NN 100000
#define NE 1000000
#define FIN 128
#define HH 8
#define HF 256
#define CC 16
#define NB_SCAN ((NN + 1023) / 1024)
#define FULL 0xFFFFFFFFu
#define XLD 136   // smem row stride: 136 % 32 == 8 -> conflict-free fragment loads

// ---------------- scratch (static device globals; no allocation) ----------------
__device__ __align__(16) __half g_h1h[NN * HF];   // fp16 features (message gather)
__device__ __align__(16) float g_out1[NN * HF];   // elu(layer-1 output)
__device__ __align__(16) float g_s1s[NN * HH];
__device__ __align__(16) float g_s1d[NN * HH];
__device__ __align__(16) float g_h2[NN * CC];
__device__ float g_s2s[NN];
__device__ float g_s2d[NN];
__device__ __align__(16) float g_w1[NE * HH];     // layer-1 edge weights (CSR order)
__device__ float g_w2[NE];                        // layer-2 edge weights (CSR order)
__device__ int g_deg[NN];
__device__ int g_cur[NN];
__device__ int g_rs[NN + 1];
__device__ int g_csrc[NE];
__device__ int g_pos[NE];                         // edge e -> CSR slot
__device__ int g_bsum[128];

// fast exp on FMA pipe (rel err ~1.5e-5 for |v| <= 20)
__device__ __forceinline__ float fast_exp(float v) {
    float t = v * 1.44269504089f;
    float fi = floorf(t);
    float f = t - fi;
    float p = 1.540353e-4f;
    p = fmaf(p, f, 1.333356e-3f);
    p = fmaf(p, f, 9.618129e-3f);
    p = fmaf(p, f, 5.550411e-2f);
    p = fmaf(p, f, 2.402265e-1f);
    p = fmaf(p, f, 6.931472e-1f);
    p = fmaf(p, f, 1.0f);
    int i = (int)fi;
    return p * __int_as_float((i + 127) << 23);
}

// round fp32 -> tf32 (bit pattern stays a valid fp32 with low mantissa cleared)
__device__ __forceinline__ float f2tf(float f) {
    uint32_t u;
    asm("cvt.rna.tf32.f32 %0, %1;" : "=r"(u) : "f"(f));
    return __uint_as_float(u);
}

__device__ __forceinline__ void mma_tf32(float* c, const uint32_t* a, const uint32_t* b) {
    asm volatile(
        "mma.sync.aligned.m16n8k8.row.col.f32.tf32.tf32.f32 "
        "{%0,%1,%2,%3}, {%4,%5,%6,%7}, {%8,%9}, {%0,%1,%2,%3};"
        : "+f"(c[0]), "+f"(c[1]), "+f"(c[2]), "+f"(c[3])
        : "r"(a[0]), "r"(a[1]), "r"(a[2]), "r"(a[3]), "r"(b[0]), "r"(b[1]));
}

// ---------------- CSR construction ----------------
__global__ void k_zero() {
    int i = blockIdx.x * blockDim.x + threadIdx.x;
    if (i < NN) g_deg[i] = 0;
}

__global__ void k_hist(const int* __restrict__ ei) {
    int e = blockIdx.x * blockDim.x + threadIdx.x;
    if (e < NE) atomicAdd(&g_deg[ei[NE + e]], 1);
}

__global__ void k_scanA() {
    __shared__ int s[1024];
    int t = threadIdx.x;
    int i = blockIdx.x * 1024 + t;
    int v = (i < NN) ? g_deg[i] : 0;
    s[t] = v;
    __syncthreads();
    for (int off = 1; off < 1024; off <<= 1) {
        int u = (t >= off) ? s[t - off] : 0;
        __syncthreads();
        s[t] += u;
        __syncthreads();
    }
    if (i < NN) g_rs[i] = s[t] - v;
    if (t == 1023) g_bsum[blockIdx.x] = s[1023];
}

__global__ void k_scanB() {
    __shared__ int s[128];
    int t = threadIdx.x;
    int v = (t < NB_SCAN) ? g_bsum[t] : 0;
    s[t] = v;
    __syncthreads();
    for (int off = 1; off < 128; off <<= 1) {
        int u = (t >= off) ? s[t - off] : 0;
        __syncthreads();
        s[t] += u;
        __syncthreads();
    }
    if (t < NB_SCAN) g_bsum[t] = s[t] - v;
}

__global__ void k_scanC() {
    int i = blockIdx.x * blockDim.x + threadIdx.x;
    if (i < NN) {
        int v = g_rs[i] + g_bsum[i >> 10];
        g_rs[i] = v;
        g_cur[i] = v;
    }
    if (i == 0) g_rs[NN] = NE;
}

__global__ void k_scatter(const int* __restrict__ ei) {
    int e = blockIdx.x * blockDim.x + threadIdx.x;
    if (e < NE) {
        int d = ei[NE + e];
        int pos = atomicAdd(&g_cur[d], 1);
        g_csrc[pos] = ei[e];
        g_pos[e] = pos;
    }
}

// ---------------- GEMM1 (tf32 tensor core) + score epilogue ----------------
// CTA tile 128x128, 8 warps (4m x 2n), warp tile 32x64 = 2x8 m16n8k8 mma tiles.
// K-tile 32, 4 chunks of k8. Inputs tf32-rounded at smem-store time.
__global__ void __launch_bounds__(256) k_gemm1(const float* __restrict__ x,
                                               const float* __restrict__ W1,
                                               const float* __restrict__ as1,
                                               const float* __restrict__ ad1) {
    __shared__ float Xs[32][XLD];  // [k][m]
    __shared__ float Ws[32][XLD];  // [k][n]
    int bm = blockIdx.x * 128;
    int bn = blockIdx.y * 128;
    int t = threadIdx.x;
    int lane = t & 31, warp = t >> 5;
    int g = lane >> 2, ctid = lane & 3;
    int wm = warp >> 1, wn = warp & 1;
    int m0w = wm * 32, n0w = wn * 64;

    float c[2][8][4];
#pragma unroll
    for (int mt = 0; mt < 2; mt++)
#pragma unroll
        for (int nt = 0; nt < 8; nt++)
#pragma unroll
            for (int q = 0; q < 4; q++) c[mt][nt][q] = 0.f;

#pragma unroll
    for (int kt = 0; kt < 4; kt++) {
        // X tile: transpose-store with tf32 rounding (conflict-free scalar STS)
#pragma unroll
        for (int it = 0; it < 4; it++) {
            int idx = t + 256 * it;            // 0..1023
            int r = idx & 127;                 // m row
            int kq = idx >> 7;                 // k quad 0..7
            int row = bm + r;
            float4 v = (row < NN)
                ? *(const float4*)(x + row * FIN + kt * 32 + kq * 4)
                : make_float4(0.f, 0.f, 0.f, 0.f);
            Xs[kq * 4 + 0][r] = f2tf(v.x);
            Xs[kq * 4 + 1][r] = f2tf(v.y);
            Xs[kq * 4 + 2][r] = f2tf(v.z);
            Xs[kq * 4 + 3][r] = f2tf(v.w);
        }
        // W tile: tf32-round in regs, vector store
#pragma unroll
        for (int it = 0; it < 4; it++) {
            int idx = t + 256 * it;
            int k = idx >> 5, nc = idx & 31;
            float4 wv = *(const float4*)(W1 + (kt * 32 + k) * HF + bn + nc * 4);
            wv.x = f2tf(wv.x); wv.y = f2tf(wv.y);
            wv.z = f2tf(wv.z); wv.w = f2tf(wv.w);
            *(float4*)&Ws[k][nc * 4] = wv;
        }
        __syncthreads();

#pragma unroll
        for (int kc = 0; kc < 4; kc++) {
            int kr = kc * 8;
            uint32_t A[2][4];
#pragma unroll
            for (int mt = 0; mt < 2; mt++) {
                int mb = m0w + mt * 16 + g;
                A[mt][0] = __float_as_uint(Xs[kr + ctid][mb]);
                A[mt][1] = __float_as_uint(Xs[kr + ctid][mb + 8]);
                A[mt][2] = __float_as_uint(Xs[kr + ctid + 4][mb]);
                A[mt][3] = __float_as_uint(Xs[kr + ctid + 4][mb + 8]);
            }
            uint32_t B[8][2];
#pragma unroll
            for (int nt = 0; nt < 8; nt++) {
                int nb = n0w + nt * 8 + g;
                B[nt][0] = __float_as_uint(Ws[kr + ctid][nb]);
                B[nt][1] = __float_as_uint(Ws[kr + ctid + 4][nb]);
            }
#pragma unroll
            for (int mt = 0; mt < 2; mt++)
#pragma unroll
                for (int nt = 0; nt < 8; nt++)
                    mma_tf32(c[mt][nt], A[mt], B[nt]);
        }
        __syncthreads();
    }

    // epilogue: fp16 feature store + per-head attention dots.
    // Warp's 64 cols = heads head0, head0+1. ctid-quad covers a row's 32 head-cols.
    int head0 = (bn >> 5) + wn * 2;
#pragma unroll
    for (int mt = 0; mt < 2; mt++) {
#pragma unroll
        for (int hf = 0; hf < 2; hf++) {
            int row = bm + m0w + mt * 16 + hf * 8 + g;
            bool ok = row < NN;
            if (ok) {
#pragma unroll
                for (int nt = 0; nt < 8; nt++) {
                    __half2 hv = __floats2half2_rn(c[mt][nt][hf * 2], c[mt][nt][hf * 2 + 1]);
                    *(__half2*)(g_h1h + row * HF + bn + n0w + nt * 8 + ctid * 2) = hv;
                }
            }
#pragma unroll
            for (int hh = 0; hh < 2; hh++) {
                float ss = 0.f, sd = 0.f;
#pragma unroll
                for (int q = 0; q < 4; q++) {
                    int col = (head0 + hh) * 32 + q * 8 + ctid * 2;
                    float v0 = c[mt][hh * 4 + q][hf * 2];
                    float v1 = c[mt][hh * 4 + q][hf * 2 + 1];
                    ss += v0 * as1[col] + v1 * as1[col + 1];
                    sd += v0 * ad1[col] + v1 * ad1[col + 1];
                }
                ss += __shfl_xor_sync(FULL, ss, 1); ss += __shfl_xor_sync(FULL, ss, 2);
                sd += __shfl_xor_sync(FULL, sd, 1); sd += __shfl_xor_sync(FULL, sd, 2);
                if (ok && ctid == 0) {
                    g_s1s[row * 8 + head0 + hh] = ss;
                    g_s1d[row * 8 + head0 + hh] = sd;
                }
            }
        }
    }
}

// ---------------- edge weights, layer 1 (no-max softmax numerator) ----------------
__global__ void k_w1(const int* __restrict__ ei) {
    int e = blockIdx.x * blockDim.x + threadIdx.x;
    if (e >= NE) return;
    int s = ei[e], d = ei[NE + e];
    int pos = g_pos[e];
    float4 ss0 = *(const float4*)&g_s1s[s * 8];
    float4 ss1 = *(const float4*)&g_s1s[s * 8 + 4];
    float4 sd0 = *(const float4*)&g_s1d[d * 8];
    float4 sd1 = *(const float4*)&g_s1d[d * 8 + 4];
    float sc[8] = {ss0.x + sd0.x, ss0.y + sd0.y, ss0.z + sd0.z, ss0.w + sd0.w,
                   ss1.x + sd1.x, ss1.y + sd1.y, ss1.z + sd1.z, ss1.w + sd1.w};
    float wv[8];
#pragma unroll
    for (int h = 0; h < 8; h++) {
        float v = sc[h] > 0.f ? sc[h] : 0.2f * sc[h];
        wv[h] = fast_exp(v);
    }
    *(float4*)&g_w1[pos * 8] = make_float4(wv[0], wv[1], wv[2], wv[3]);
    *(float4*)&g_w1[pos * 8 + 4] = make_float4(wv[4], wv[5], wv[6], wv[7]);
}

// ---------------- layer-1 aggregation: warp per dst node, 2-edge unroll, fused sum ----------------
__global__ void __launch_bounds__(256) k_agg1(const float* __restrict__ b1) {
    int gt = blockIdx.x * blockDim.x + threadIdx.x;
    int w = gt >> 5;
    int lane = threadIdx.x & 31;
    if (w >= NN) return;
    int rs = g_rs[w];
    int deg = g_rs[w + 1] - rs;
    int lh = lane & 7;
    int hsub = lane >> 4;

    float sm = 0.f;
    float acc[8] = {0.f, 0.f, 0.f, 0.f, 0.f, 0.f, 0.f, 0.f};
    int j = 0;
    for (; j + 2 <= deg; j += 2) {
        int p0 = rs + j, p1 = rs + j + 1;
        int s0 = g_csrc[p0], s1 = g_csrc[p1];
        float w0 = g_w1[p0 * 8 + lh];
        float w1 = g_w1[p1 * 8 + lh];
        sm += w0 + w1;
        const __half2* hp0 = (const __half2*)(g_h1h + s0 * HF);
        const __half2* hp1 = (const __half2*)(g_h1h + s1 * HF);
#pragma unroll
        for (int k = 0; k < 4; k++) {
            float2 f0 = __half22float2(hp0[k * 32 + lane]);
            float2 f1 = __half22float2(hp1[k * 32 + lane]);
            float wk0 = __shfl_sync(FULL, w0, k * 2 + hsub);
            float wk1 = __shfl_sync(FULL, w1, k * 2 + hsub);
            acc[2 * k]     += wk0 * f0.x + wk1 * f1.x;
            acc[2 * k + 1] += wk0 * f0.y + wk1 * f1.y;
        }
    }
    if (j < deg) {
        int p0 = rs + j;
        int s0 = g_csrc[p0];
        float w0 = g_w1[p0 * 8 + lh];
        sm += w0;
        const __half2* hp0 = (const __half2*)(g_h1h + s0 * HF);
#pragma unroll
        for (int k = 0; k < 4; k++) {
            float2 f0 = __half22float2(hp0[k * 32 + lane]);
            float wk0 = __shfl_sync(FULL, w0, k * 2 + hsub);
            acc[2 * k]     += wk0 * f0.x;
            acc[2 * k + 1] += wk0 * f0.y;
        }
    }
    float inv = 1.f / (sm + 1e-16f);

#pragma unroll
    for (int k = 0; k < 4; k++) {
        float invk = __shfl_sync(FULL, inv, k * 2 + hsub);
        int f = k * 64 + lane * 2;
        float2 bv = *(const float2*)&b1[f];
        float o0 = acc[2 * k] * invk + bv.x;
        float o1 = acc[2 * k + 1] * invk + bv.y;
        o0 = o0 > 0.f ? o0 : expm1f(o0);
        o1 = o1 > 0.f ? o1 : expm1f(o1);
        *(float2*)&g_out1[w * HF + f] = make_float2(o0, o1);
    }
}

// ---------------- GEMM2 + layer-2 attention dots: warp per node ----------------
__global__ void k_gemm2(const float* __restrict__ W2, const float* __restrict__ as2,
                        const float* __restrict__ ad2) {
    __shared__ float W2t[16][256];
    int t = threadIdx.x;
    for (int i = t; i < 4096; i += blockDim.x) {
        int k = i >> 4, c = i & 15;
        W2t[c][k] = W2[i];
    }
    __syncthreads();
    int lane = t & 31, wid = t >> 5;
    for (int n = blockIdx.x * 8 + wid; n < NN; n += gridDim.x * 8) {
        const float* xp = g_out1 + n * HF;
        float v[8];
#pragma unroll
        for (int k = 0; k < 8; k++) v[k] = xp[k * 32 + lane];
        float acc[16];
#pragma unroll
        for (int c = 0; c < 16; c++) acc[c] = 0.f;
#pragma unroll
        for (int k = 0; k < 8; k++)
#pragma unroll
            for (int c = 0; c < 16; c++) acc[c] += v[k] * W2t[c][k * 32 + lane];
#pragma unroll
        for (int c = 0; c < 16; c++)
#pragma unroll
            for (int off = 16; off; off >>= 1)
                acc[c] += __shfl_xor_sync(FULL, acc[c], off);
        float h2v = acc[0];
#pragma unroll
        for (int c = 1; c < 16; c++)
            if ((lane & 15) == c) h2v = acc[c];
        if (lane < 16) g_h2[n * CC + lane] = h2v;
        float ps = (lane < 16) ? h2v * as2[lane] : 0.f;
        float pd = (lane < 16) ? h2v * ad2[lane] : 0.f;
#pragma unroll
        for (int off = 16; off; off >>= 1) {
            ps += __shfl_xor_sync(FULL, ps, off);
            pd += __shfl_xor_sync(FULL, pd, off);
        }
        if (lane == 0) { g_s2s[n] = ps; g_s2d[n] = pd; }
    }
}

// ---------------- edge weights, layer 2 ----------------
__global__ void k_w2(const int* __restrict__ ei) {
    int e = blockIdx.x * blockDim.x + threadIdx.x;
    if (e >= NE) return;
    int s = ei[e], d = ei[NE + e];
    float sc = g_s2s[s] + g_s2d[d];
    sc = sc > 0.f ? sc : 0.2f * sc;
    g_w2[g_pos[e]] = fast_exp(sc);
}

// ---------------- layer-2 aggregation ----------------
__global__ void __launch_bounds__(256) k_agg2(const float* __restrict__ b2,
                                              float* __restrict__ out) {
    int gt = blockIdx.x * blockDim.x + threadIdx.x;
    int w = gt >> 5;
    int lane = threadIdx.x & 31;
    if (w >= NN) return;
    int rs = g_rs[w];
    int deg = g_rs[w + 1] - rs;
    int half = lane >> 4, l15 = lane & 15;

    float sm = 0.f;
    float acc = 0.f;
    for (int j = half; j < deg; j += 2) {
        int p = rs + j;
        int s = g_csrc[p];
        float wv = g_w2[p];
        sm += wv;
        acc += wv * g_h2[s * CC + l15];
    }
    acc += __shfl_xor_sync(FULL, acc, 16);
    sm += __shfl_xor_sync(FULL, sm, 16);
    float inv = 1.f / (sm + 1e-16f);
    if (lane < 16) out[w * CC + l15] = acc * inv + b2[l15];
}

// ---------------- launch ----------------
extern "C" void kernel_launch(void* const* d_in, const int* in_sizes, int n_in,
                              void* d_out, int out_size) {
    const float* x = (const float*)d_in[0];
    const int* ei = (const int*)d_in[1];
    const float* W1 = (const float*)d_in[2];
    const float* as1 = (const float*)d_in[3];
    const float* ad1 = (const float*)d_in[4];
    const float* b1 = (const float*)d_in[5];
    const float* W2 = (const float*)d_in[6];
    const float* as2 = (const float*)d_in[7];
    const float* ad2 = (const float*)d_in[8];
    const float* b2 = (const float*)d_in[9];
    float* out = (float*)d_out;

    // CSR build (gemm1 placed 4th so ncu's skip window keeps capturing it)
    k_zero<<<(NN + 255) / 256, 256>>>();
    k_hist<<<(NE + 255) / 256, 256>>>(ei);
    k_scanA<<<NB_SCAN, 1024>>>();
    k_gemm1<<<dim3((NN + 127) / 128, 2), 256>>>(x, W1, as1, ad1);
    k_scanB<<<1, 128>>>();
    k_scanC<<<(NN + 255) / 256, 256>>>();
    k_scatter<<<(NE + 255) / 256, 256>>>(ei);

    // layer 1
    k_w1<<<(NE + 255) / 256, 256>>>(ei);
    k_agg1<<<(NN * 32 + 255) / 256, 256>>>(b1);

    // layer 2
    k_gemm2<<<1024, 256>>>(W2, as2, ad2);
    k_w2<<<(NE + 255) / 256, 256>>>(ei);
    k_agg2<<<(NN * 32 + 255) / 256, 256>>>(b2, out);
}

// round 12
// speedup vs baseline: 1.2382x; 1.0679x over previous
#include <cuda_runtime.h>
#include <cuda_fp16.h>
#include <cstdint>

#define NN 100000
#define NE 1000000
#define FIN 128
#define HH 8
#define HF 256
#define CC 16
#define NB_SCAN ((NN + 1023) / 1024)
#define FULL 0xFFFFFFFFu

// ---------------- scratch (static device globals; no allocation) ----------------
__device__ __align__(16) __half g_h1h[NN * HF];   // fp16 features (message gather)
__device__ __align__(16) float g_out1[NN * HF];   // elu(layer-1 output)
__device__ __align__(16) float g_s1s[NN * HH];
__device__ __align__(16) float g_s1d[NN * HH];
__device__ __align__(16) float g_h2[NN * CC];
__device__ float g_s2s[NN];
__device__ float g_s2d[NN];
__device__ __align__(16) float g_w1[NE * HH];     // layer-1 edge weights (CSR order)
__device__ float g_w2[NE];                        // layer-2 edge weights (CSR order)
__device__ int g_deg[NN];
__device__ int g_cur[NN];
__device__ int g_rs[NN + 1];
__device__ int g_csrc[NE];
__device__ int g_pos[NE];                         // edge e -> CSR slot
__device__ int g_bsum[128];

// fast exp on FMA pipe (rel err ~1.5e-5 for |v| <= 20)
__device__ __forceinline__ float fast_exp(float v) {
    float t = v * 1.44269504089f;
    float fi = floorf(t);
    float f = t - fi;
    float p = 1.540353e-4f;
    p = fmaf(p, f, 1.333356e-3f);
    p = fmaf(p, f, 9.618129e-3f);
    p = fmaf(p, f, 5.550411e-2f);
    p = fmaf(p, f, 2.402265e-1f);
    p = fmaf(p, f, 6.931472e-1f);
    p = fmaf(p, f, 1.0f);
    int i = (int)fi;
    return p * __int_as_float((i + 127) << 23);
}

__device__ __forceinline__ uint32_t s2u(const void* p) {
    return (uint32_t)__cvta_generic_to_shared(p);
}

#define LDMX4(r0, r1, r2, r3, addr) \
    asm volatile("ldmatrix.sync.aligned.m8n8.x4.shared.b16 {%0,%1,%2,%3}, [%4];" \
                 : "=r"(r0), "=r"(r1), "=r"(r2), "=r"(r3) : "r"(addr))

#define LDMX4T(r0, r1, r2, r3, addr) \
    asm volatile("ldmatrix.sync.aligned.m8n8.x4.trans.shared.b16 {%0,%1,%2,%3}, [%4];" \
                 : "=r"(r0), "=r"(r1), "=r"(r2), "=r"(r3) : "r"(addr))

__device__ __forceinline__ void mma_f16(float* c, const uint32_t* a,
                                        uint32_t b0, uint32_t b1) {
    asm volatile(
        "mma.sync.aligned.m16n8k16.row.col.f32.f16.f16.f32 "
        "{%0,%1,%2,%3}, {%4,%5,%6,%7}, {%8,%9}, {%0,%1,%2,%3};"
        : "+f"(c[0]), "+f"(c[1]), "+f"(c[2]), "+f"(c[3])
        : "r"(a[0]), "r"(a[1]), "r"(a[2]), "r"(a[3]), "r"(b0), "r"(b1));
}

// ---------------- CSR construction ----------------
__global__ void k_zero() {
    int i = blockIdx.x * blockDim.x + threadIdx.x;
    if (i < NN) g_deg[i] = 0;
}

__global__ void k_hist(const int* __restrict__ ei) {
    int e = blockIdx.x * blockDim.x + threadIdx.x;
    if (e < NE) atomicAdd(&g_deg[ei[NE + e]], 1);
}

__global__ void k_scanA() {
    __shared__ int s[1024];
    int t = threadIdx.x;
    int i = blockIdx.x * 1024 + t;
    int v = (i < NN) ? g_deg[i] : 0;
    s[t] = v;
    __syncthreads();
    for (int off = 1; off < 1024; off <<= 1) {
        int u = (t >= off) ? s[t - off] : 0;
        __syncthreads();
        s[t] += u;
        __syncthreads();
    }
    if (i < NN) g_rs[i] = s[t] - v;
    if (t == 1023) g_bsum[blockIdx.x] = s[1023];
}

__global__ void k_scanB() {
    __shared__ int s[128];
    int t = threadIdx.x;
    int v = (t < NB_SCAN) ? g_bsum[t] : 0;
    s[t] = v;
    __syncthreads();
    for (int off = 1; off < 128; off <<= 1) {
        int u = (t >= off) ? s[t - off] : 0;
        __syncthreads();
        s[t] += u;
        __syncthreads();
    }
    if (t < NB_SCAN) g_bsum[t] = s[t] - v;
}

__global__ void k_scanC() {
    int i = blockIdx.x * blockDim.x + threadIdx.x;
    if (i < NN) {
        int v = g_rs[i] + g_bsum[i >> 10];
        g_rs[i] = v;
        g_cur[i] = v;
    }
    if (i == 0) g_rs[NN] = NE;
}

__global__ void k_scatter(const int* __restrict__ ei) {
    int e = blockIdx.x * blockDim.x + threadIdx.x;
    if (e < NE) {
        int d = ei[NE + e];
        int pos = atomicAdd(&g_cur[d], 1);
        g_csrc[pos] = ei[e];
        g_pos[e] = pos;
    }
}

// ---------------- GEMM1 (fp16 tensor core + ldmatrix) + score epilogue ----------------
// CTA tile 128x128, 8 warps (4m x 2n), warp tile 32x64 = 2x8 m16n8k16 tiles.
// K-tile 64 (2 chunks of FIN=128). Smem strides: Xh 72 halves (36 words),
// Wh 136 halves (68 words) -- both ≡ 4 (mod 32) => conflict-free ldmatrix.
__global__ void __launch_bounds__(256) k_gemm1(const float* __restrict__ x,
                                               const float* __restrict__ W1,
                                               const float* __restrict__ as1,
                                               const float* __restrict__ ad1) {
    __shared__ __align__(16) __half Xh[128][72];   // [m][k]
    __shared__ __align__(16) __half Wh[64][136];   // [k][n]
    int bm = blockIdx.x * 128;
    int bn = blockIdx.y * 128;
    int t = threadIdx.x;
    int lane = t & 31, warp = t >> 5;
    int g = lane >> 2, ctid = lane & 3;
    int wm = warp >> 1, wn = warp & 1;
    int m0w = wm * 32, n0w = wn * 64;
    int l15 = lane & 15, lhi = lane >> 4;

    float c[2][8][4];
#pragma unroll
    for (int mt = 0; mt < 2; mt++)
#pragma unroll
        for (int nt = 0; nt < 8; nt++)
#pragma unroll
            for (int q = 0; q < 4; q++) c[mt][nt][q] = 0.f;

#pragma unroll
    for (int kt = 0; kt < 2; kt++) {
        // X tile: 128 rows x 64 k, fp16 convert, natural [m][k] layout
#pragma unroll
        for (int it = 0; it < 8; it++) {
            int idx = t + 256 * it;            // 0..2047
            int r = idx >> 4, kq = idx & 15;
            int row = bm + r;
            float4 v = (row < NN)
                ? *(const float4*)(x + row * FIN + kt * 64 + kq * 4)
                : make_float4(0.f, 0.f, 0.f, 0.f);
            *(__half2*)&Xh[r][kq * 4]     = __floats2half2_rn(v.x, v.y);
            *(__half2*)&Xh[r][kq * 4 + 2] = __floats2half2_rn(v.z, v.w);
        }
        // W tile: 64 k x 128 n, fp16 convert, natural [k][n] layout
#pragma unroll
        for (int it = 0; it < 8; it++) {
            int idx = t + 256 * it;
            int k = idx >> 5, nc = idx & 31;
            float4 wv = *(const float4*)(W1 + (kt * 64 + k) * HF + bn + nc * 4);
            *(__half2*)&Wh[k][nc * 4]     = __floats2half2_rn(wv.x, wv.y);
            *(__half2*)&Wh[k][nc * 4 + 2] = __floats2half2_rn(wv.z, wv.w);
        }
        __syncthreads();

#pragma unroll
        for (int kc = 0; kc < 4; kc++) {
            int kr = kc * 16;
            uint32_t A[2][4];
#pragma unroll
            for (int mt = 0; mt < 2; mt++) {
                uint32_t addr = s2u(&Xh[m0w + mt * 16 + l15][kr + lhi * 8]);
                LDMX4(A[mt][0], A[mt][1], A[mt][2], A[mt][3], addr);
            }
            uint32_t B[4][4];
#pragma unroll
            for (int p = 0; p < 4; p++) {
                uint32_t addr = s2u(&Wh[kr + l15][n0w + p * 16 + lhi * 8]);
                LDMX4T(B[p][0], B[p][1], B[p][2], B[p][3], addr);
            }
#pragma unroll
            for (int mt = 0; mt < 2; mt++)
#pragma unroll
                for (int p = 0; p < 4; p++) {
                    mma_f16(c[mt][2 * p],     A[mt], B[p][0], B[p][1]);
                    mma_f16(c[mt][2 * p + 1], A[mt], B[p][2], B[p][3]);
                }
        }
        __syncthreads();
    }

    // epilogue: fp16 feature store + per-head attention dots (unchanged layout)
    int head0 = (bn >> 5) + wn * 2;
#pragma unroll
    for (int mt = 0; mt < 2; mt++) {
#pragma unroll
        for (int hf = 0; hf < 2; hf++) {
            int row = bm + m0w + mt * 16 + hf * 8 + g;
            bool ok = row < NN;
            if (ok) {
#pragma unroll
                for (int nt = 0; nt < 8; nt++) {
                    __half2 hv = __floats2half2_rn(c[mt][nt][hf * 2], c[mt][nt][hf * 2 + 1]);
                    *(__half2*)(g_h1h + row * HF + bn + n0w + nt * 8 + ctid * 2) = hv;
                }
            }
#pragma unroll
            for (int hh = 0; hh < 2; hh++) {
                float ss = 0.f, sd = 0.f;
#pragma unroll
                for (int q = 0; q < 4; q++) {
                    int col = (head0 + hh) * 32 + q * 8 + ctid * 2;
                    float v0 = c[mt][hh * 4 + q][hf * 2];
                    float v1 = c[mt][hh * 4 + q][hf * 2 + 1];
                    ss += v0 * as1[col] + v1 * as1[col + 1];
                    sd += v0 * ad1[col] + v1 * ad1[col + 1];
                }
                ss += __shfl_xor_sync(FULL, ss, 1); ss += __shfl_xor_sync(FULL, ss, 2);
                sd += __shfl_xor_sync(FULL, sd, 1); sd += __shfl_xor_sync(FULL, sd, 2);
                if (ok && ctid == 0) {
                    g_s1s[row * 8 + head0 + hh] = ss;
                    g_s1d[row * 8 + head0 + hh] = sd;
                }
            }
        }
    }
}

// ---------------- edge weights, layer 1 (no-max softmax numerator) ----------------
__global__ void k_w1(const int* __restrict__ ei) {
    int e = blockIdx.x * blockDim.x + threadIdx.x;
    if (e >= NE) return;
    int s = ei[e], d = ei[NE + e];
    int pos = g_pos[e];
    float4 ss0 = *(const float4*)&g_s1s[s * 8];
    float4 ss1 = *(const float4*)&g_s1s[s * 8 + 4];
    float4 sd0 = *(const float4*)&g_s1d[d * 8];
    float4 sd1 = *(const float4*)&g_s1d[d * 8 + 4];
    float sc[8] = {ss0.x + sd0.x, ss0.y + sd0.y, ss0.z + sd0.z, ss0.w + sd0.w,
                   ss1.x + sd1.x, ss1.y + sd1.y, ss1.z + sd1.z, ss1.w + sd1.w};
    float wv[8];
#pragma unroll
    for (int h = 0; h < 8; h++) {
        float v = sc[h] > 0.f ? sc[h] : 0.2f * sc[h];
        wv[h] = fast_exp(v);
    }
    *(float4*)&g_w1[pos * 8] = make_float4(wv[0], wv[1], wv[2], wv[3]);
    *(float4*)&g_w1[pos * 8 + 4] = make_float4(wv[4], wv[5], wv[6], wv[7]);
}

// ---------------- layer-1 aggregation: warp per dst node, 2-edge unroll, fused sum ----------------
__global__ void __launch_bounds__(256) k_agg1(const float* __restrict__ b1) {
    int gt = blockIdx.x * blockDim.x + threadIdx.x;
    int w = gt >> 5;
    int lane = threadIdx.x & 31;
    if (w >= NN) return;
    int rs = g_rs[w];
    int deg = g_rs[w + 1] - rs;
    int lh = lane & 7;
    int hsub = lane >> 4;

    float sm = 0.f;
    float acc[8] = {0.f, 0.f, 0.f, 0.f, 0.f, 0.f, 0.f, 0.f};
    int j = 0;
    for (; j + 2 <= deg; j += 2) {
        int p0 = rs + j, p1 = rs + j + 1;
        int s0 = g_csrc[p0], s1 = g_csrc[p1];
        float w0 = g_w1[p0 * 8 + lh];
        float w1 = g_w1[p1 * 8 + lh];
        sm += w0 + w1;
        const __half2* hp0 = (const __half2*)(g_h1h + s0 * HF);
        const __half2* hp1 = (const __half2*)(g_h1h + s1 * HF);
#pragma unroll
        for (int k = 0; k < 4; k++) {
            float2 f0 = __half22float2(hp0[k * 32 + lane]);
            float2 f1 = __half22float2(hp1[k * 32 + lane]);
            float wk0 = __shfl_sync(FULL, w0, k * 2 + hsub);
            float wk1 = __shfl_sync(FULL, w1, k * 2 + hsub);
            acc[2 * k]     += wk0 * f0.x + wk1 * f1.x;
            acc[2 * k + 1] += wk0 * f0.y + wk1 * f1.y;
        }
    }
    if (j < deg) {
        int p0 = rs + j;
        int s0 = g_csrc[p0];
        float w0 = g_w1[p0 * 8 + lh];
        sm += w0;
        const __half2* hp0 = (const __half2*)(g_h1h + s0 * HF);
#pragma unroll
        for (int k = 0; k < 4; k++) {
            float2 f0 = __half22float2(hp0[k * 32 + lane]);
            float wk0 = __shfl_sync(FULL, w0, k * 2 + hsub);
            acc[2 * k]     += wk0 * f0.x;
            acc[2 * k + 1] += wk0 * f0.y;
        }
    }
    float inv = 1.f / (sm + 1e-16f);

#pragma unroll
    for (int k = 0; k < 4; k++) {
        float invk = __shfl_sync(FULL, inv, k * 2 + hsub);
        int f = k * 64 + lane * 2;
        float2 bv = *(const float2*)&b1[f];
        float o0 = acc[2 * k] * invk + bv.x;
        float o1 = acc[2 * k + 1] * invk + bv.y;
        o0 = o0 > 0.f ? o0 : expm1f(o0);
        o1 = o1 > 0.f ? o1 : expm1f(o1);
        *(float2*)&g_out1[w * HF + f] = make_float2(o0, o1);
    }
}

// ---------------- GEMM2 + layer-2 attention dots: warp per node ----------------
__global__ void k_gemm2(const float* __restrict__ W2, const float* __restrict__ as2,
                        const float* __restrict__ ad2) {
    __shared__ float W2t[16][256];
    int t = threadIdx.x;
    for (int i = t; i < 4096; i += blockDim.x) {
        int k = i >> 4, c = i & 15;
        W2t[c][k] = W2[i];
    }
    __syncthreads();
    int lane = t & 31, wid = t >> 5;
    for (int n = blockIdx.x * 8 + wid; n < NN; n += gridDim.x * 8) {
        const float* xp = g_out1 + n * HF;
        float v[8];
#pragma unroll
        for (int k = 0; k < 8; k++) v[k] = xp[k * 32 + lane];
        float acc[16];
#pragma unroll
        for (int c = 0; c < 16; c++) acc[c] = 0.f;
#pragma unroll
        for (int k = 0; k < 8; k++)
#pragma unroll
            for (int c = 0; c < 16; c++) acc[c] += v[k] * W2t[c][k * 32 + lane];
#pragma unroll
        for (int c = 0; c < 16; c++)
#pragma unroll
            for (int off = 16; off; off >>= 1)
                acc[c] += __shfl_xor_sync(FULL, acc[c], off);
        float h2v = acc[0];
#pragma unroll
        for (int c = 1; c < 16; c++)
            if ((lane & 15) == c) h2v = acc[c];
        if (lane < 16) g_h2[n * CC + lane] = h2v;
        float ps = (lane < 16) ? h2v * as2[lane] : 0.f;
        float pd = (lane < 16) ? h2v * ad2[lane] : 0.f;
#pragma unroll
        for (int off = 16; off; off >>= 1) {
            ps += __shfl_xor_sync(FULL, ps, off);
            pd += __shfl_xor_sync(FULL, pd, off);
        }
        if (lane == 0) { g_s2s[n] = ps; g_s2d[n] = pd; }
    }
}

// ---------------- edge weights, layer 2 ----------------
__global__ void k_w2(const int* __restrict__ ei) {
    int e = blockIdx.x * blockDim.x + threadIdx.x;
    if (e >= NE) return;
    int s = ei[e], d = ei[NE + e];
    float sc = g_s2s[s] + g_s2d[d];
    sc = sc > 0.f ? sc : 0.2f * sc;
    g_w2[g_pos[e]] = fast_exp(sc);
}

// ---------------- layer-2 aggregation ----------------
__global__ void __launch_bounds__(256) k_agg2(const float* __restrict__ b2,
                                              float* __restrict__ out) {
    int gt = blockIdx.x * blockDim.x + threadIdx.x;
    int w = gt >> 5;
    int lane = threadIdx.x & 31;
    if (w >= NN) return;
    int rs = g_rs[w];
    int deg = g_rs[w + 1] - rs;
    int half = lane >> 4, l15 = lane & 15;

    float sm = 0.f;
    float acc = 0.f;
    for (int j = half; j < deg; j += 2) {
        int p = rs + j;
        int s = g_csrc[p];
        float wv = g_w2[p];
        sm += wv;
        acc += wv * g_h2[s * CC + l15];
    }
    acc += __shfl_xor_sync(FULL, acc, 16);
    sm += __shfl_xor_sync(FULL, sm, 16);
    float inv = 1.f / (sm + 1e-16f);
    if (lane < 16) out[w * CC + l15] = acc * inv + b2[l15];
}

// ---------------- launch ----------------
extern "C" void kernel_launch(void* const* d_in, const int* in_sizes, int n_in,
                              void* d_out, int out_size) {
    const float* x = (const float*)d_in[0];
    const int* ei = (const int*)d_in[1];
    const float* W1 = (const float*)d_in[2];
    const float* as1 = (const float*)d_in[3];
    const float* ad1 = (const float*)d_in[4];
    const float* b1 = (const float*)d_in[5];
    const float* W2 = (const float*)d_in[6];
    const float* as2 = (const float*)d_in[7];
    const float* ad2 = (const float*)d_in[8];
    const float* b2 = (const float*)d_in[9];
    float* out = (float*)d_out;

    // CSR build (gemm1 placed 4th so ncu's skip window keeps capturing it)
    k_zero<<<(NN + 255) / 256, 256>>>();
    k_hist<<<(NE + 255) / 256, 256>>>(ei);
    k_scanA<<<NB_SCAN, 1024>>>();
    k_gemm1<<<dim3((NN + 127) / 128, 2), 256>>>(x, W1, as1, ad1);
    k_scanB<<<1, 128>>>();
    k_scanC<<<(NN + 255) / 256, 256>>>();
    k_scatter<<<(NE + 255) / 256, 256>>>(ei);

    // layer 1
    k_w1<<<(NE + 255) / 256, 256>>>(ei);
    k_agg1<<<(NN * 32 + 255) / 256, 256>>>(b1);

    // layer 2
    k_gemm2<<<1024, 256>>>(W2, as2, ad2);
    k_w2<<<(NE + 255) / 256, 256>>>(ei);
    k_agg2<<<(NN * 32 + 255) / 256, 256>>>(b2, out);
}

// round 13
// speedup vs baseline: 1.3144x; 1.0615x over previous
#include <cuda_runtime.h>
#include <cuda_fp16.h>
#include <cstdint>

#define NN 100000
#define NE 1000000
#define FIN 128
#define HH 8
#define HF 256
#define CC 16
#define NB_SCAN ((NN + 1023) / 1024)
#define FULL 0xFFFFFFFFu

// ---------------- scratch (static device globals; no allocation) ----------------
__device__ __align__(16) __half g_h1h[NN * HF];   // fp16 features (message gather)
__device__ __align__(16) float g_out1[NN * HF];   // elu(layer-1 output)
__device__ __align__(16) float g_s1s[NN * HH];
__device__ __align__(16) float g_s1d[NN * HH];
__device__ __align__(16) float g_h2[NN * CC];
__device__ float g_s2s[NN];
__device__ float g_s2d[NN];
__device__ int g_deg[NN];
__device__ int g_cur[NN];
__device__ int g_rs[NN + 1];
__device__ int g_csrc[NE];
__device__ int g_bsum[128];

// fast exp on FMA pipe (rel err ~1.5e-5 for |v| <= 20)
__device__ __forceinline__ float fast_exp(float v) {
    float t = v * 1.44269504089f;
    float fi = floorf(t);
    float f = t - fi;
    float p = 1.540353e-4f;
    p = fmaf(p, f, 1.333356e-3f);
    p = fmaf(p, f, 9.618129e-3f);
    p = fmaf(p, f, 5.550411e-2f);
    p = fmaf(p, f, 2.402265e-1f);
    p = fmaf(p, f, 6.931472e-1f);
    p = fmaf(p, f, 1.0f);
    int i = (int)fi;
    return p * __int_as_float((i + 127) << 23);
}

// leaky-relu then fast_exp
__device__ __forceinline__ float lexp(float sc) {
    float v = sc > 0.f ? sc : 0.2f * sc;
    return fast_exp(v);
}

__device__ __forceinline__ uint32_t s2u(const void* p) {
    return (uint32_t)__cvta_generic_to_shared(p);
}

#define LDMX4(r0, r1, r2, r3, addr) \
    asm volatile("ldmatrix.sync.aligned.m8n8.x4.shared.b16 {%0,%1,%2,%3}, [%4];" \
                 : "=r"(r0), "=r"(r1), "=r"(r2), "=r"(r3) : "r"(addr))

#define LDMX4T(r0, r1, r2, r3, addr) \
    asm volatile("ldmatrix.sync.aligned.m8n8.x4.trans.shared.b16 {%0,%1,%2,%3}, [%4];" \
                 : "=r"(r0), "=r"(r1), "=r"(r2), "=r"(r3) : "r"(addr))

__device__ __forceinline__ void mma_f16(float* c, const uint32_t* a,
                                        uint32_t b0, uint32_t b1) {
    asm volatile(
        "mma.sync.aligned.m16n8k16.row.col.f32.f16.f16.f32 "
        "{%0,%1,%2,%3}, {%4,%5,%6,%7}, {%8,%9}, {%0,%1,%2,%3};"
        : "+f"(c[0]), "+f"(c[1]), "+f"(c[2]), "+f"(c[3])
        : "r"(a[0]), "r"(a[1]), "r"(a[2]), "r"(a[3]), "r"(b0), "r"(b1));
}

// ---------------- CSR construction ----------------
__global__ void k_zero() {
    int i = blockIdx.x * blockDim.x + threadIdx.x;
    if (i < NN) g_deg[i] = 0;
}

__global__ void k_hist(const int* __restrict__ ei) {
    int e = blockIdx.x * blockDim.x + threadIdx.x;
    if (e < NE) atomicAdd(&g_deg[ei[NE + e]], 1);
}

__global__ void k_scanA() {
    __shared__ int s[1024];
    int t = threadIdx.x;
    int i = blockIdx.x * 1024 + t;
    int v = (i < NN) ? g_deg[i] : 0;
    s[t] = v;
    __syncthreads();
    for (int off = 1; off < 1024; off <<= 1) {
        int u = (t >= off) ? s[t - off] : 0;
        __syncthreads();
        s[t] += u;
        __syncthreads();
    }
    if (i < NN) g_rs[i] = s[t] - v;
    if (t == 1023) g_bsum[blockIdx.x] = s[1023];
}

__global__ void k_scanB() {
    __shared__ int s[128];
    int t = threadIdx.x;
    int v = (t < NB_SCAN) ? g_bsum[t] : 0;
    s[t] = v;
    __syncthreads();
    for (int off = 1; off < 128; off <<= 1) {
        int u = (t >= off) ? s[t - off] : 0;
        __syncthreads();
        s[t] += u;
        __syncthreads();
    }
    if (t < NB_SCAN) g_bsum[t] = s[t] - v;
}

__global__ void k_scanC() {
    int i = blockIdx.x * blockDim.x + threadIdx.x;
    if (i < NN) {
        int v = g_rs[i] + g_bsum[i >> 10];
        g_rs[i] = v;
        g_cur[i] = v;
    }
    if (i == 0) g_rs[NN] = NE;
}

__global__ void k_scatter(const int* __restrict__ ei) {
    int e = blockIdx.x * blockDim.x + threadIdx.x;
    if (e < NE) {
        int d = ei[NE + e];
        int pos = atomicAdd(&g_cur[d], 1);
        g_csrc[pos] = ei[e];
    }
}

// ---------------- GEMM1 (fp16 tensor core + ldmatrix) + score epilogue ----------------
// CTA tile 128x128, 8 warps (4m x 2n), warp tile 32x64 = 2x8 m16n8k16 tiles.
__global__ void __launch_bounds__(256) k_gemm1(const float* __restrict__ x,
                                               const float* __restrict__ W1,
                                               const float* __restrict__ as1,
                                               const float* __restrict__ ad1) {
    __shared__ __align__(16) __half Xh[128][72];   // [m][k]
    __shared__ __align__(16) __half Wh[64][136];   // [k][n]
    int bm = blockIdx.x * 128;
    int bn = blockIdx.y * 128;
    int t = threadIdx.x;
    int lane = t & 31, warp = t >> 5;
    int g = lane >> 2, ctid = lane & 3;
    int wm = warp >> 1, wn = warp & 1;
    int m0w = wm * 32, n0w = wn * 64;
    int l15 = lane & 15, lhi = lane >> 4;

    float c[2][8][4];
#pragma unroll
    for (int mt = 0; mt < 2; mt++)
#pragma unroll
        for (int nt = 0; nt < 8; nt++)
#pragma unroll
            for (int q = 0; q < 4; q++) c[mt][nt][q] = 0.f;

#pragma unroll
    for (int kt = 0; kt < 2; kt++) {
#pragma unroll
        for (int it = 0; it < 8; it++) {
            int idx = t + 256 * it;            // 0..2047
            int r = idx >> 4, kq = idx & 15;
            int row = bm + r;
            float4 v = (row < NN)
                ? *(const float4*)(x + row * FIN + kt * 64 + kq * 4)
                : make_float4(0.f, 0.f, 0.f, 0.f);
            *(__half2*)&Xh[r][kq * 4]     = __floats2half2_rn(v.x, v.y);
            *(__half2*)&Xh[r][kq * 4 + 2] = __floats2half2_rn(v.z, v.w);
        }
#pragma unroll
        for (int it = 0; it < 8; it++) {
            int idx = t + 256 * it;
            int k = idx >> 5, nc = idx & 31;
            float4 wv = *(const float4*)(W1 + (kt * 64 + k) * HF + bn + nc * 4);
            *(__half2*)&Wh[k][nc * 4]     = __floats2half2_rn(wv.x, wv.y);
            *(__half2*)&Wh[k][nc * 4 + 2] = __floats2half2_rn(wv.z, wv.w);
        }
        __syncthreads();

#pragma unroll
        for (int kc = 0; kc < 4; kc++) {
            int kr = kc * 16;
            uint32_t A[2][4];
#pragma unroll
            for (int mt = 0; mt < 2; mt++) {
                uint32_t addr = s2u(&Xh[m0w + mt * 16 + l15][kr + lhi * 8]);
                LDMX4(A[mt][0], A[mt][1], A[mt][2], A[mt][3], addr);
            }
            uint32_t B[4][4];
#pragma unroll
            for (int p = 0; p < 4; p++) {
                uint32_t addr = s2u(&Wh[kr + l15][n0w + p * 16 + lhi * 8]);
                LDMX4T(B[p][0], B[p][1], B[p][2], B[p][3], addr);
            }
#pragma unroll
            for (int mt = 0; mt < 2; mt++)
#pragma unroll
                for (int p = 0; p < 4; p++) {
                    mma_f16(c[mt][2 * p],     A[mt], B[p][0], B[p][1]);
                    mma_f16(c[mt][2 * p + 1], A[mt], B[p][2], B[p][3]);
                }
        }
        __syncthreads();
    }

    int head0 = (bn >> 5) + wn * 2;
#pragma unroll
    for (int mt = 0; mt < 2; mt++) {
#pragma unroll
        for (int hf = 0; hf < 2; hf++) {
            int row = bm + m0w + mt * 16 + hf * 8 + g;
            bool ok = row < NN;
            if (ok) {
#pragma unroll
                for (int nt = 0; nt < 8; nt++) {
                    __half2 hv = __floats2half2_rn(c[mt][nt][hf * 2], c[mt][nt][hf * 2 + 1]);
                    *(__half2*)(g_h1h + row * HF + bn + n0w + nt * 8 + ctid * 2) = hv;
                }
            }
#pragma unroll
            for (int hh = 0; hh < 2; hh++) {
                float ss = 0.f, sd = 0.f;
#pragma unroll
                for (int q = 0; q < 4; q++) {
                    int col = (head0 + hh) * 32 + q * 8 + ctid * 2;
                    float v0 = c[mt][hh * 4 + q][hf * 2];
                    float v1 = c[mt][hh * 4 + q][hf * 2 + 1];
                    ss += v0 * as1[col] + v1 * as1[col + 1];
                    sd += v0 * ad1[col] + v1 * ad1[col + 1];
                }
                ss += __shfl_xor_sync(FULL, ss, 1); ss += __shfl_xor_sync(FULL, ss, 2);
                sd += __shfl_xor_sync(FULL, sd, 1); sd += __shfl_xor_sync(FULL, sd, 2);
                if (ok && ctid == 0) {
                    g_s1s[row * 8 + head0 + hh] = ss;
                    g_s1d[row * 8 + head0 + hh] = sd;
                }
            }
        }
    }
}

// ---------------- layer-1 aggregation: warp per dst node, inline edge weights ----------------
// Lane lh = lane&7 computes its head's weight from per-node scores directly
// (no materialized g_w1): w = exp(leaky(s1s[src][lh] + s1d[dst][lh])).
__global__ void __launch_bounds__(256) k_agg1(const float* __restrict__ b1) {
    int gt = blockIdx.x * blockDim.x + threadIdx.x;
    int w = gt >> 5;
    int lane = threadIdx.x & 31;
    if (w >= NN) return;
    int rs = g_rs[w];
    int deg = g_rs[w + 1] - rs;
    int lh = lane & 7;
    int hsub = lane >> 4;

    float sdl = g_s1d[w * 8 + lh];   // dst score for this lane's head

    float sm = 0.f;
    float acc[8] = {0.f, 0.f, 0.f, 0.f, 0.f, 0.f, 0.f, 0.f};
    int j = 0;
    for (; j + 2 <= deg; j += 2) {
        int s0 = g_csrc[rs + j], s1 = g_csrc[rs + j + 1];
        float w0 = lexp(g_s1s[s0 * 8 + lh] + sdl);
        float w1 = lexp(g_s1s[s1 * 8 + lh] + sdl);
        sm += w0 + w1;
        const __half2* hp0 = (const __half2*)(g_h1h + s0 * HF);
        const __half2* hp1 = (const __half2*)(g_h1h + s1 * HF);
#pragma unroll
        for (int k = 0; k < 4; k++) {
            float2 f0 = __half22float2(hp0[k * 32 + lane]);
            float2 f1 = __half22float2(hp1[k * 32 + lane]);
            float wk0 = __shfl_sync(FULL, w0, k * 2 + hsub);
            float wk1 = __shfl_sync(FULL, w1, k * 2 + hsub);
            acc[2 * k]     += wk0 * f0.x + wk1 * f1.x;
            acc[2 * k + 1] += wk0 * f0.y + wk1 * f1.y;
        }
    }
    if (j < deg) {
        int s0 = g_csrc[rs + j];
        float w0 = lexp(g_s1s[s0 * 8 + lh] + sdl);
        sm += w0;
        const __half2* hp0 = (const __half2*)(g_h1h + s0 * HF);
#pragma unroll
        for (int k = 0; k < 4; k++) {
            float2 f0 = __half22float2(hp0[k * 32 + lane]);
            float wk0 = __shfl_sync(FULL, w0, k * 2 + hsub);
            acc[2 * k]     += wk0 * f0.x;
            acc[2 * k + 1] += wk0 * f0.y;
        }
    }
    sm += __shfl_xor_sync(FULL, sm, 8);      // combine the two lane-groups per head
    sm += __shfl_xor_sync(FULL, sm, 16);
    // NOTE: lanes with same lh (lane, lane^8, lane^16, lane^24) computed identical
    // partial sums over the SAME edges (all lanes walk all edges) -> sm is now 4x.
    float inv = 1.f / (sm * 0.25f + 1e-16f);

#pragma unroll
    for (int k = 0; k < 4; k++) {
        float invk = __shfl_sync(FULL, inv, k * 2 + hsub);
        int f = k * 64 + lane * 2;
        float2 bv = *(const float2*)&b1[f];
        float o0 = acc[2 * k] * invk + bv.x;
        float o1 = acc[2 * k + 1] * invk + bv.y;
        o0 = o0 > 0.f ? o0 : expm1f(o0);
        o1 = o1 > 0.f ? o1 : expm1f(o1);
        *(float2*)&g_out1[w * HF + f] = make_float2(o0, o1);
    }
}

// ---------------- GEMM2 + layer-2 attention dots: warp per node ----------------
__global__ void k_gemm2(const float* __restrict__ W2, const float* __restrict__ as2,
                        const float* __restrict__ ad2) {
    __shared__ float W2t[16][256];
    int t = threadIdx.x;
    for (int i = t; i < 4096; i += blockDim.x) {
        int k = i >> 4, c = i & 15;
        W2t[c][k] = W2[i];
    }
    __syncthreads();
    int lane = t & 31, wid = t >> 5;
    for (int n = blockIdx.x * 8 + wid; n < NN; n += gridDim.x * 8) {
        const float* xp = g_out1 + n * HF;
        float v[8];
#pragma unroll
        for (int k = 0; k < 8; k++) v[k] = xp[k * 32 + lane];
        float acc[16];
#pragma unroll
        for (int c = 0; c < 16; c++) acc[c] = 0.f;
#pragma unroll
        for (int k = 0; k < 8; k++)
#pragma unroll
            for (int c = 0; c < 16; c++) acc[c] += v[k] * W2t[c][k * 32 + lane];
#pragma unroll
        for (int c = 0; c < 16; c++)
#pragma unroll
            for (int off = 16; off; off >>= 1)
                acc[c] += __shfl_xor_sync(FULL, acc[c], off);
        float h2v = acc[0];
#pragma unroll
        for (int c = 1; c < 16; c++)
            if ((lane & 15) == c) h2v = acc[c];
        if (lane < 16) g_h2[n * CC + lane] = h2v;
        float ps = (lane < 16) ? h2v * as2[lane] : 0.f;
        float pd = (lane < 16) ? h2v * ad2[lane] : 0.f;
#pragma unroll
        for (int off = 16; off; off >>= 1) {
            ps += __shfl_xor_sync(FULL, ps, off);
            pd += __shfl_xor_sync(FULL, pd, off);
        }
        if (lane == 0) { g_s2s[n] = ps; g_s2d[n] = pd; }
    }
}

// ---------------- layer-2 aggregation: inline edge weights ----------------
__global__ void __launch_bounds__(256) k_agg2(const float* __restrict__ b2,
                                              float* __restrict__ out) {
    int gt = blockIdx.x * blockDim.x + threadIdx.x;
    int w = gt >> 5;
    int lane = threadIdx.x & 31;
    if (w >= NN) return;
    int rs = g_rs[w];
    int deg = g_rs[w + 1] - rs;
    int half = lane >> 4, l15 = lane & 15;

    float sd = g_s2d[w];
    float sm = 0.f;
    float acc = 0.f;
    for (int j = half; j < deg; j += 2) {
        int s = g_csrc[rs + j];
        float wv = lexp(g_s2s[s] + sd);
        sm += wv;
        acc += wv * g_h2[s * CC + l15];
    }
    acc += __shfl_xor_sync(FULL, acc, 16);
    sm += __shfl_xor_sync(FULL, sm, 16);
    float inv = 1.f / (sm + 1e-16f);
    if (lane < 16) out[w * CC + l15] = acc * inv + b2[l15];
}

// ---------------- launch ----------------
extern "C" void kernel_launch(void* const* d_in, const int* in_sizes, int n_in,
                              void* d_out, int out_size) {
    const float* x = (const float*)d_in[0];
    const int* ei = (const int*)d_in[1];
    const float* W1 = (const float*)d_in[2];
    const float* as1 = (const float*)d_in[3];
    const float* ad1 = (const float*)d_in[4];
    const float* b1 = (const float*)d_in[5];
    const float* W2 = (const float*)d_in[6];
    const float* as2 = (const float*)d_in[7];
    const float* ad2 = (const float*)d_in[8];
    const float* b2 = (const float*)d_in[9];
    float* out = (float*)d_out;

    // CSR build (gemm1 placed 4th so ncu's skip window keeps capturing it)
    k_zero<<<(NN + 255) / 256, 256>>>();
    k_hist<<<(NE + 255) / 256, 256>>>(ei);
    k_scanA<<<NB_SCAN, 1024>>>();
    k_gemm1<<<dim3((NN + 127) / 128, 2), 256>>>(x, W1, as1, ad1);
    k_scanB<<<1, 128>>>();
    k_scanC<<<(NN + 255) / 256, 256>>>();
    k_scatter<<<(NE + 255) / 256, 256>>>(ei);

    // layer 1
    k_agg1<<<(NN * 32 + 255) / 256, 256>>>(b1);

    // layer 2
    k_gemm2<<<1024, 256>>>(W2, as2, ad2);
    k_agg2<<<(NN * 32 + 255) / 256, 256>>>(b2, out);
}

// round 16
// speedup vs baseline: 1.7598x; 1.3389x over previous
#include <cuda_runtime.h>
#include <cuda_fp16.h>
#include <cstdint>

#define NN 100000
#define NE 1000000
#define FIN 128
#define HH 8
#define HF 256
#define CC 16
#define NB_SCAN ((NN + 1023) / 1024)
#define FULL 0xFFFFFFFFu

// ---------------- scratch (static device globals; no allocation) ----------------
__device__ __align__(16) __half g_h1h[NN * HF];   // fp16 layer-1 features (gather)
__device__ __align__(16) __half g_out1h[NN * HF]; // fp16 elu(layer-1 output)
__device__ __align__(16) float g_s1s[NN * HH];
__device__ __align__(16) float g_s1d[NN * HH];
__device__ __align__(16) float g_h2[NN * CC];
__device__ float g_s2s[NN];
__device__ float g_s2d[NN];
__device__ int g_deg[NN];
__device__ int g_cur[NN];
__device__ int g_rs[NN + 1];
__device__ int g_csrc[NE];
__device__ int g_bsum[128];

// fast exp on FMA pipe (rel err ~1.5e-5 for |v| <= 20)
__device__ __forceinline__ float fast_exp(float v) {
    float t = v * 1.44269504089f;
    float fi = floorf(t);
    float f = t - fi;
    float p = 1.540353e-4f;
    p = fmaf(p, f, 1.333356e-3f);
    p = fmaf(p, f, 9.618129e-3f);
    p = fmaf(p, f, 5.550411e-2f);
    p = fmaf(p, f, 2.402265e-1f);
    p = fmaf(p, f, 6.931472e-1f);
    p = fmaf(p, f, 1.0f);
    int i = (int)fi;
    return p * __int_as_float((i + 127) << 23);
}

__device__ __forceinline__ float lexp(float sc) {
    float v = sc > 0.f ? sc : 0.2f * sc;
    return fast_exp(v);
}

__device__ __forceinline__ uint32_t s2u(const void* p) {
    return (uint32_t)__cvta_generic_to_shared(p);
}

#define LDMX4(r0, r1, r2, r3, addr) \
    asm volatile("ldmatrix.sync.aligned.m8n8.x4.shared.b16 {%0,%1,%2,%3}, [%4];" \
                 : "=r"(r0), "=r"(r1), "=r"(r2), "=r"(r3) : "r"(addr))

#define LDMX4T(r0, r1, r2, r3, addr) \
    asm volatile("ldmatrix.sync.aligned.m8n8.x4.trans.shared.b16 {%0,%1,%2,%3}, [%4];" \
                 : "=r"(r0), "=r"(r1), "=r"(r2), "=r"(r3) : "r"(addr))

__device__ __forceinline__ void mma_f16(float* c, const uint32_t* a,
                                        uint32_t b0, uint32_t b1) {
    asm volatile(
        "mma.sync.aligned.m16n8k16.row.col.f32.f16.f16.f32 "
        "{%0,%1,%2,%3}, {%4,%5,%6,%7}, {%8,%9}, {%0,%1,%2,%3};"
        : "+f"(c[0]), "+f"(c[1]), "+f"(c[2]), "+f"(c[3])
        : "r"(a[0]), "r"(a[1]), "r"(a[2]), "r"(a[3]), "r"(b0), "r"(b1));
}

// ---------------- CSR construction ----------------
__global__ void k_zero() {
    int i = blockIdx.x * blockDim.x + threadIdx.x;
    if (i < NN) g_deg[i] = 0;
}

__global__ void k_hist(const int* __restrict__ ei) {
    int e = blockIdx.x * blockDim.x + threadIdx.x;
    if (e < NE) atomicAdd(&g_deg[ei[NE + e]], 1);
}

__global__ void k_scanA() {
    __shared__ int s[1024];
    int t = threadIdx.x;
    int i = blockIdx.x * 1024 + t;
    int v = (i < NN) ? g_deg[i] : 0;
    s[t] = v;
    __syncthreads();
    for (int off = 1; off < 1024; off <<= 1) {
        int u = (t >= off) ? s[t - off] : 0;
        __syncthreads();
        s[t] += u;
        __syncthreads();
    }
    if (i < NN) g_rs[i] = s[t] - v;
    if (t == 1023) g_bsum[blockIdx.x] = s[1023];
}

__global__ void k_scanB() {
    __shared__ int s[128];
    int t = threadIdx.x;
    int v = (t < NB_SCAN) ? g_bsum[t] : 0;
    s[t] = v;
    __syncthreads();
    for (int off = 1; off < 128; off <<= 1) {
        int u = (t >= off) ? s[t - off] : 0;
        __syncthreads();
        s[t] += u;
        __syncthreads();
    }
    if (t < NB_SCAN) g_bsum[t] = s[t] - v;
}

__global__ void k_scanC() {
    int i = blockIdx.x * blockDim.x + threadIdx.x;
    if (i < NN) {
        int v = g_rs[i] + g_bsum[i >> 10];
        g_rs[i] = v;
        g_cur[i] = v;
    }
    if (i == 0) g_rs[NN] = NE;
}

__global__ void k_scatter(const int* __restrict__ ei) {
    int e = blockIdx.x * blockDim.x + threadIdx.x;
    if (e < NE) {
        int d = ei[NE + e];
        int pos = atomicAdd(&g_cur[d], 1);
        g_csrc[pos] = ei[e];
    }
}

// ---------------- GEMM1 (fp16 tensor core + ldmatrix) + score epilogue ----------------
__global__ void __launch_bounds__(256) k_gemm1(const float* __restrict__ x,
                                               const float* __restrict__ W1,
                                               const float* __restrict__ as1,
                                               const float* __restrict__ ad1) {
    __shared__ __align__(16) __half Xh[128][72];   // [m][k]
    __shared__ __align__(16) __half Wh[64][136];   // [k][n]
    int bm = blockIdx.x * 128;
    int bn = blockIdx.y * 128;
    int t = threadIdx.x;
    int lane = t & 31, warp = t >> 5;
    int g = lane >> 2, ctid = lane & 3;
    int wm = warp >> 1, wn = warp & 1;
    int m0w = wm * 32, n0w = wn * 64;
    int l15 = lane & 15, lhi = lane >> 4;

    float c[2][8][4];
#pragma unroll
    for (int mt = 0; mt < 2; mt++)
#pragma unroll
        for (int nt = 0; nt < 8; nt++)
#pragma unroll
            for (int q = 0; q < 4; q++) c[mt][nt][q] = 0.f;

#pragma unroll
    for (int kt = 0; kt < 2; kt++) {
#pragma unroll
        for (int it = 0; it < 8; it++) {
            int idx = t + 256 * it;            // 0..2047
            int r = idx >> 4, kq = idx & 15;
            int row = bm + r;
            float4 v = (row < NN)
                ? *(const float4*)(x + row * FIN + kt * 64 + kq * 4)
                : make_float4(0.f, 0.f, 0.f, 0.f);
            *(__half2*)&Xh[r][kq * 4]     = __floats2half2_rn(v.x, v.y);
            *(__half2*)&Xh[r][kq * 4 + 2] = __floats2half2_rn(v.z, v.w);
        }
#pragma unroll
        for (int it = 0; it < 8; it++) {
            int idx = t + 256 * it;
            int k = idx >> 5, nc = idx & 31;
            float4 wv = *(const float4*)(W1 + (kt * 64 + k) * HF + bn + nc * 4);
            *(__half2*)&Wh[k][nc * 4]     = __floats2half2_rn(wv.x, wv.y);
            *(__half2*)&Wh[k][nc * 4 + 2] = __floats2half2_rn(wv.z, wv.w);
        }
        __syncthreads();

#pragma unroll
        for (int kc = 0; kc < 4; kc++) {
            int kr = kc * 16;
            uint32_t A[2][4];
#pragma unroll
            for (int mt = 0; mt < 2; mt++) {
                uint32_t addr = s2u(&Xh[m0w + mt * 16 + l15][kr + lhi * 8]);
                LDMX4(A[mt][0], A[mt][1], A[mt][2], A[mt][3], addr);
            }
            uint32_t B[4][4];
#pragma unroll
            for (int p = 0; p < 4; p++) {
                uint32_t addr = s2u(&Wh[kr + l15][n0w + p * 16 + lhi * 8]);
                LDMX4T(B[p][0], B[p][1], B[p][2], B[p][3], addr);
            }
#pragma unroll
            for (int mt = 0; mt < 2; mt++)
#pragma unroll
                for (int p = 0; p < 4; p++) {
                    mma_f16(c[mt][2 * p],     A[mt], B[p][0], B[p][1]);
                    mma_f16(c[mt][2 * p + 1], A[mt], B[p][2], B[p][3]);
                }
        }
        __syncthreads();
    }

    int head0 = (bn >> 5) + wn * 2;
#pragma unroll
    for (int mt = 0; mt < 2; mt++) {
#pragma unroll
        for (int hf = 0; hf < 2; hf++) {
            int row = bm + m0w + mt * 16 + hf * 8 + g;
            bool ok = row < NN;
            if (ok) {
#pragma unroll
                for (int nt = 0; nt < 8; nt++) {
                    __half2 hv = __floats2half2_rn(c[mt][nt][hf * 2], c[mt][nt][hf * 2 + 1]);
                    *(__half2*)(g_h1h + row * HF + bn + n0w + nt * 8 + ctid * 2) = hv;
                }
            }
#pragma unroll
            for (int hh = 0; hh < 2; hh++) {
                float ss = 0.f, sd = 0.f;
#pragma unroll
                for (int q = 0; q < 4; q++) {
                    int col = (head0 + hh) * 32 + q * 8 + ctid * 2;
                    float v0 = c[mt][hh * 4 + q][hf * 2];
                    float v1 = c[mt][hh * 4 + q][hf * 2 + 1];
                    ss += v0 * as1[col] + v1 * as1[col + 1];
                    sd += v0 * ad1[col] + v1 * ad1[col + 1];
                }
                ss += __shfl_xor_sync(FULL, ss, 1); ss += __shfl_xor_sync(FULL, ss, 2);
                sd += __shfl_xor_sync(FULL, sd, 1); sd += __shfl_xor_sync(FULL, sd, 2);
                if (ok && ctid == 0) {
                    g_s1s[row * 8 + head0 + hh] = ss;
                    g_s1d[row * 8 + head0 + hh] = sd;
                }
            }
        }
    }
}

// ---------------- layer-1 aggregation: 2 warps per dst node, inline edge weights ----------------
__global__ void __launch_bounds__(256) k_agg1(const float* __restrict__ b1) {
    __shared__ float red[4][32][9];    // [pair][lane][acc0..7, sm]
    int warp = threadIdx.x >> 5;
    int lane = threadIdx.x & 31;
    int pairi = warp >> 1;
    int half = warp & 1;
    int w = blockIdx.x * 4 + pairi;    // NN % 4 == 0 -> always valid
    int rs = g_rs[w];
    int deg = g_rs[w + 1] - rs;
    int lh = lane & 7;
    int hsub = lane >> 4;

    float sdl = g_s1d[w * 8 + lh];

    int mid = deg >> 1;
    int jb = half ? mid : 0;
    int je = half ? deg : mid;

    float sm = 0.f;
    float acc[8] = {0.f, 0.f, 0.f, 0.f, 0.f, 0.f, 0.f, 0.f};
    int j = jb;
    for (; j + 2 <= je; j += 2) {
        int s0 = g_csrc[rs + j], s1 = g_csrc[rs + j + 1];
        float w0 = lexp(g_s1s[s0 * 8 + lh] + sdl);
        float w1 = lexp(g_s1s[s1 * 8 + lh] + sdl);
        sm += w0 + w1;
        const __half2* hp0 = (const __half2*)(g_h1h + s0 * HF);
        const __half2* hp1 = (const __half2*)(g_h1h + s1 * HF);
#pragma unroll
        for (int k = 0; k < 4; k++) {
            float2 f0 = __half22float2(hp0[k * 32 + lane]);
            float2 f1 = __half22float2(hp1[k * 32 + lane]);
            float wk0 = __shfl_sync(FULL, w0, k * 2 + hsub);
            float wk1 = __shfl_sync(FULL, w1, k * 2 + hsub);
            acc[2 * k]     += wk0 * f0.x + wk1 * f1.x;
            acc[2 * k + 1] += wk0 * f0.y + wk1 * f1.y;
        }
    }
    if (j < je) {
        int s0 = g_csrc[rs + j];
        float w0 = lexp(g_s1s[s0 * 8 + lh] + sdl);
        sm += w0;
        const __half2* hp0 = (const __half2*)(g_h1h + s0 * HF);
#pragma unroll
        for (int k = 0; k < 4; k++) {
            float2 f0 = __half22float2(hp0[k * 32 + lane]);
            float wk0 = __shfl_sync(FULL, w0, k * 2 + hsub);
            acc[2 * k]     += wk0 * f0.x;
            acc[2 * k + 1] += wk0 * f0.y;
        }
    }

    if (half) {
#pragma unroll
        for (int k = 0; k < 8; k++) red[pairi][lane][k] = acc[k];
        red[pairi][lane][8] = sm;
    }
    __syncthreads();
    if (!half) {
#pragma unroll
        for (int k = 0; k < 8; k++) acc[k] += red[pairi][lane][k];
        sm += red[pairi][lane][8];
        sm += __shfl_xor_sync(FULL, sm, 8);
        sm += __shfl_xor_sync(FULL, sm, 16);
        // 4 lanes per head hold identical full sums -> divide by 4
        float inv = 1.f / (sm * 0.25f + 1e-16f);
#pragma unroll
        for (int k = 0; k < 4; k++) {
            float invk = __shfl_sync(FULL, inv, k * 2 + hsub);
            int f = k * 64 + lane * 2;
            float2 bv = *(const float2*)&b1[f];
            float o0 = acc[2 * k] * invk + bv.x;
            float o1 = acc[2 * k + 1] * invk + bv.y;
            o0 = o0 > 0.f ? o0 : expm1f(o0);
            o1 = o1 > 0.f ? o1 : expm1f(o1);
            *(__half2*)(g_out1h + w * HF + f) = __floats2half2_rn(o0, o1);
        }
    }
}

// ---------------- GEMM2 + layer-2 attention dots: warp per 2 nodes ----------------
// fp16 input rows are 128 half2 wide -> k loop is 4 iterations (32 half2 each).
__global__ void k_gemm2(const float* __restrict__ W2, const float* __restrict__ as2,
                        const float* __restrict__ ad2) {
    __shared__ float W2t[16][256];
    int t = threadIdx.x;
    for (int i = t; i < 4096; i += blockDim.x) {
        int k = i >> 4, c = i & 15;
        W2t[c][k] = W2[i];
    }
    __syncthreads();
    int lane = t & 31, wid = t >> 5;
    for (int n0 = blockIdx.x * 16 + wid * 2; n0 < NN; n0 += gridDim.x * 16) {
        const __half2* xa = (const __half2*)(g_out1h + n0 * HF);
        const __half2* xb = (const __half2*)(g_out1h + (n0 + 1) * HF);
        float accA[16], accB[16];
#pragma unroll
        for (int c = 0; c < 16; c++) { accA[c] = 0.f; accB[c] = 0.f; }
#pragma unroll
        for (int k = 0; k < 4; k++) {              // 4 x 32 half2 = 256 halves/row
            float2 fa = __half22float2(xa[k * 32 + lane]);
            float2 fb = __half22float2(xb[k * 32 + lane]);
            int fw = k * 64 + lane * 2;            // feature index of fa.x
#pragma unroll
            for (int c = 0; c < 16; c++) {
                float2 wv = *(const float2*)&W2t[c][fw];
                accA[c] += fa.x * wv.x + fa.y * wv.y;
                accB[c] += fb.x * wv.x + fb.y * wv.y;
            }
        }
#pragma unroll
        for (int c = 0; c < 16; c++)
#pragma unroll
            for (int off = 16; off; off >>= 1) {
                accA[c] += __shfl_xor_sync(FULL, accA[c], off);
                accB[c] += __shfl_xor_sync(FULL, accB[c], off);
            }
        // node n0
        {
            float h2v = accA[0];
#pragma unroll
            for (int c = 1; c < 16; c++)
                if ((lane & 15) == c) h2v = accA[c];
            if (lane < 16) g_h2[n0 * CC + lane] = h2v;
            float ps = (lane < 16) ? h2v * as2[lane] : 0.f;
            float pd = (lane < 16) ? h2v * ad2[lane] : 0.f;
#pragma unroll
            for (int off = 16; off; off >>= 1) {
                ps += __shfl_xor_sync(FULL, ps, off);
                pd += __shfl_xor_sync(FULL, pd, off);
            }
            if (lane == 0) { g_s2s[n0] = ps; g_s2d[n0] = pd; }
        }
        // node n0+1
        {
            float h2v = accB[0];
#pragma unroll
            for (int c = 1; c < 16; c++)
                if ((lane & 15) == c) h2v = accB[c];
            if (lane < 16) g_h2[(n0 + 1) * CC + lane] = h2v;
            float ps = (lane < 16) ? h2v * as2[lane] : 0.f;
            float pd = (lane < 16) ? h2v * ad2[lane] : 0.f;
#pragma unroll
            for (int off = 16; off; off >>= 1) {
                ps += __shfl_xor_sync(FULL, ps, off);
                pd += __shfl_xor_sync(FULL, pd, off);
            }
            if (lane == 0) { g_s2s[n0 + 1] = ps; g_s2d[n0 + 1] = pd; }
        }
    }
}

// ---------------- layer-2 aggregation: inline edge weights ----------------
__global__ void __launch_bounds__(256) k_agg2(const float* __restrict__ b2,
                                              float* __restrict__ out) {
    int gt = blockIdx.x * blockDim.x + threadIdx.x;
    int w = gt >> 5;
    int lane = threadIdx.x & 31;
    if (w >= NN) return;
    int rs = g_rs[w];
    int deg = g_rs[w + 1] - rs;
    int half = lane >> 4, l15 = lane & 15;

    float sd = g_s2d[w];
    float sm = 0.f;
    float acc = 0.f;
    for (int j = half; j < deg; j += 2) {
        int s = g_csrc[rs + j];
        float wv = lexp(g_s2s[s] + sd);
        sm += wv;
        acc += wv * g_h2[s * CC + l15];
    }
    acc += __shfl_xor_sync(FULL, acc, 16);
    sm += __shfl_xor_sync(FULL, sm, 16);
    float inv = 1.f / (sm + 1e-16f);
    if (lane < 16) out[w * CC + l15] = acc * inv + b2[l15];
}

// ---------------- launch ----------------
extern "C" void kernel_launch(void* const* d_in, const int* in_sizes, int n_in,
                              void* d_out, int out_size) {
    const float* x = (const float*)d_in[0];
    const int* ei = (const int*)d_in[1];
    const float* W1 = (const float*)d_in[2];
    const float* as1 = (const float*)d_in[3];
    const float* ad1 = (const float*)d_in[4];
    const float* b1 = (const float*)d_in[5];
    const float* W2 = (const float*)d_in[6];
    const float* as2 = (const float*)d_in[7];
    const float* ad2 = (const float*)d_in[8];
    const float* b2 = (const float*)d_in[9];
    float* out = (float*)d_out;

    // CSR build (gemm1 placed 4th so ncu's skip window keeps capturing it)
    k_zero<<<(NN + 255) / 256, 256>>>();
    k_hist<<<(NE + 255) / 256, 256>>>(ei);
    k_scanA<<<NB_SCAN, 1024>>>();
    k_gemm1<<<dim3((NN + 127) / 128, 2), 256>>>(x, W1, as1, ad1);
    k_scanB<<<1, 128>>>();
    k_scanC<<<(NN + 255) / 256, 256>>>();
    k_scatter<<<(NE + 255) / 256, 256>>>(ei);

    // layer 1: 2 warps per node
    k_agg1<<<NN / 4, 256>>>(b1);

    // layer 2
    k_gemm2<<<1024, 256>>>(W2, as2, ad2);
    k_agg2<<<(NN * 32 + 255) / 256, 256>>>(b2, out);
}

// round 17
// speedup vs baseline: 1.8111x; 1.0292x over previous
#include <cuda_runtime.h>
#include <cuda_fp16.h>
#include <cstdint>

#define NN 100000
#define NE 1000000
#define FIN 128
#define HH 8
#define HF 256
#define CC 16
#define NB_SCAN ((NN + 1023) / 1024)
#define FULL 0xFFFFFFFFu

// ---------------- scratch (static device globals; no allocation) ----------------
__device__ __align__(16) __half g_h1h[NN * HF];   // fp16 layer-1 features (gather)
__device__ __align__(16) __half g_out1h[NN * HF]; // fp16 elu(layer-1 output)
__device__ __align__(16) float g_s1s[NN * HH];
__device__ __align__(16) float g_s1d[NN * HH];
__device__ __align__(16) float g_h2[NN * CC];
__device__ float g_s2s[NN];
__device__ float g_s2d[NN];
__device__ int g_deg[NN];
__device__ int g_cur[NN];
__device__ int g_rs[NN + 1];
__device__ int g_csrc[NE];
__device__ int g_bsum[128];

// fast exp on FMA pipe (rel err ~1.5e-5 for |v| <= 20)
__device__ __forceinline__ float fast_exp(float v) {
    float t = v * 1.44269504089f;
    float fi = floorf(t);
    float f = t - fi;
    float p = 1.540353e-4f;
    p = fmaf(p, f, 1.333356e-3f);
    p = fmaf(p, f, 9.618129e-3f);
    p = fmaf(p, f, 5.550411e-2f);
    p = fmaf(p, f, 2.402265e-1f);
    p = fmaf(p, f, 6.931472e-1f);
    p = fmaf(p, f, 1.0f);
    int i = (int)fi;
    return p * __int_as_float((i + 127) << 23);
}

__device__ __forceinline__ float lexp(float sc) {
    float v = sc > 0.f ? sc : 0.2f * sc;
    return fast_exp(v);
}

__device__ __forceinline__ uint32_t s2u(const void* p) {
    return (uint32_t)__cvta_generic_to_shared(p);
}

#define LDMX4(r0, r1, r2, r3, addr) \
    asm volatile("ldmatrix.sync.aligned.m8n8.x4.shared.b16 {%0,%1,%2,%3}, [%4];" \
                 : "=r"(r0), "=r"(r1), "=r"(r2), "=r"(r3) : "r"(addr))

#define LDMX4T(r0, r1, r2, r3, addr) \
    asm volatile("ldmatrix.sync.aligned.m8n8.x4.trans.shared.b16 {%0,%1,%2,%3}, [%4];" \
                 : "=r"(r0), "=r"(r1), "=r"(r2), "=r"(r3) : "r"(addr))

__device__ __forceinline__ void mma_f16(float* c, const uint32_t* a,
                                        uint32_t b0, uint32_t b1) {
    asm volatile(
        "mma.sync.aligned.m16n8k16.row.col.f32.f16.f16.f32 "
        "{%0,%1,%2,%3}, {%4,%5,%6,%7}, {%8,%9}, {%0,%1,%2,%3};"
        : "+f"(c[0]), "+f"(c[1]), "+f"(c[2]), "+f"(c[3])
        : "r"(a[0]), "r"(a[1]), "r"(a[2]), "r"(a[3]), "r"(b0), "r"(b1));
}

// ---------------- CSR construction ----------------
__global__ void k_zero() {
    int i = blockIdx.x * blockDim.x + threadIdx.x;
    if (i < NN) g_deg[i] = 0;
}

__global__ void k_hist(const int* __restrict__ ei) {
    int e = blockIdx.x * blockDim.x + threadIdx.x;
    if (e < NE) atomicAdd(&g_deg[ei[NE + e]], 1);
}

__global__ void k_scanA() {
    __shared__ int s[1024];
    int t = threadIdx.x;
    int i = blockIdx.x * 1024 + t;
    int v = (i < NN) ? g_deg[i] : 0;
    s[t] = v;
    __syncthreads();
    for (int off = 1; off < 1024; off <<= 1) {
        int u = (t >= off) ? s[t - off] : 0;
        __syncthreads();
        s[t] += u;
        __syncthreads();
    }
    if (i < NN) g_rs[i] = s[t] - v;
    if (t == 1023) g_bsum[blockIdx.x] = s[1023];
}

__global__ void k_scanB() {
    __shared__ int s[128];
    int t = threadIdx.x;
    int v = (t < NB_SCAN) ? g_bsum[t] : 0;
    s[t] = v;
    __syncthreads();
    for (int off = 1; off < 128; off <<= 1) {
        int u = (t >= off) ? s[t - off] : 0;
        __syncthreads();
        s[t] += u;
        __syncthreads();
    }
    if (t < NB_SCAN) g_bsum[t] = s[t] - v;
}

__global__ void k_scanC() {
    int i = blockIdx.x * blockDim.x + threadIdx.x;
    if (i < NN) {
        int v = g_rs[i] + g_bsum[i >> 10];
        g_rs[i] = v;
        g_cur[i] = v;
    }
    if (i == 0) g_rs[NN] = NE;
}

__global__ void k_scatter(const int* __restrict__ ei) {
    int e = blockIdx.x * blockDim.x + threadIdx.x;
    if (e < NE) {
        int d = ei[NE + e];
        int pos = atomicAdd(&g_cur[d], 1);
        g_csrc[pos] = ei[e];
    }
}

// ---------------- GEMM1 (fp16 tensor core + ldmatrix) + score epilogue ----------------
__global__ void __launch_bounds__(256) k_gemm1(const float* __restrict__ x,
                                               const float* __restrict__ W1,
                                               const float* __restrict__ as1,
                                               const float* __restrict__ ad1) {
    __shared__ __align__(16) __half Xh[128][72];   // [m][k]
    __shared__ __align__(16) __half Wh[64][136];   // [k][n]
    int bm = blockIdx.x * 128;
    int bn = blockIdx.y * 128;
    int t = threadIdx.x;
    int lane = t & 31, warp = t >> 5;
    int g = lane >> 2, ctid = lane & 3;
    int wm = warp >> 1, wn = warp & 1;
    int m0w = wm * 32, n0w = wn * 64;
    int l15 = lane & 15, lhi = lane >> 4;

    float c[2][8][4];
#pragma unroll
    for (int mt = 0; mt < 2; mt++)
#pragma unroll
        for (int nt = 0; nt < 8; nt++)
#pragma unroll
            for (int q = 0; q < 4; q++) c[mt][nt][q] = 0.f;

#pragma unroll
    for (int kt = 0; kt < 2; kt++) {
#pragma unroll
        for (int it = 0; it < 8; it++) {
            int idx = t + 256 * it;            // 0..2047
            int r = idx >> 4, kq = idx & 15;
            int row = bm + r;
            float4 v = (row < NN)
                ? *(const float4*)(x + row * FIN + kt * 64 + kq * 4)
                : make_float4(0.f, 0.f, 0.f, 0.f);
            *(__half2*)&Xh[r][kq * 4]     = __floats2half2_rn(v.x, v.y);
            *(__half2*)&Xh[r][kq * 4 + 2] = __floats2half2_rn(v.z, v.w);
        }
#pragma unroll
        for (int it = 0; it < 8; it++) {
            int idx = t + 256 * it;
            int k = idx >> 5, nc = idx & 31;
            float4 wv = *(const float4*)(W1 + (kt * 64 + k) * HF + bn + nc * 4);
            *(__half2*)&Wh[k][nc * 4]     = __floats2half2_rn(wv.x, wv.y);
            *(__half2*)&Wh[k][nc * 4 + 2] = __floats2half2_rn(wv.z, wv.w);
        }
        __syncthreads();

#pragma unroll
        for (int kc = 0; kc < 4; kc++) {
            int kr = kc * 16;
            uint32_t A[2][4];
#pragma unroll
            for (int mt = 0; mt < 2; mt++) {
                uint32_t addr = s2u(&Xh[m0w + mt * 16 + l15][kr + lhi * 8]);
                LDMX4(A[mt][0], A[mt][1], A[mt][2], A[mt][3], addr);
            }
            uint32_t B[4][4];
#pragma unroll
            for (int p = 0; p < 4; p++) {
                uint32_t addr = s2u(&Wh[kr + l15][n0w + p * 16 + lhi * 8]);
                LDMX4T(B[p][0], B[p][1], B[p][2], B[p][3], addr);
            }
#pragma unroll
            for (int mt = 0; mt < 2; mt++)
#pragma unroll
                for (int p = 0; p < 4; p++) {
                    mma_f16(c[mt][2 * p],     A[mt], B[p][0], B[p][1]);
                    mma_f16(c[mt][2 * p + 1], A[mt], B[p][2], B[p][3]);
                }
        }
        __syncthreads();
    }

    int head0 = (bn >> 5) + wn * 2;
#pragma unroll
    for (int mt = 0; mt < 2; mt++) {
#pragma unroll
        for (int hf = 0; hf < 2; hf++) {
            int row = bm + m0w + mt * 16 + hf * 8 + g;
            bool ok = row < NN;
            if (ok) {
#pragma unroll
                for (int nt = 0; nt < 8; nt++) {
                    __half2 hv = __floats2half2_rn(c[mt][nt][hf * 2], c[mt][nt][hf * 2 + 1]);
                    *(__half2*)(g_h1h + row * HF + bn + n0w + nt * 8 + ctid * 2) = hv;
                }
            }
#pragma unroll
            for (int hh = 0; hh < 2; hh++) {
                float ss = 0.f, sd = 0.f;
#pragma unroll
                for (int q = 0; q < 4; q++) {
                    int col = (head0 + hh) * 32 + q * 8 + ctid * 2;
                    float v0 = c[mt][hh * 4 + q][hf * 2];
                    float v1 = c[mt][hh * 4 + q][hf * 2 + 1];
                    ss += v0 * as1[col] + v1 * as1[col + 1];
                    sd += v0 * ad1[col] + v1 * ad1[col + 1];
                }
                ss += __shfl_xor_sync(FULL, ss, 1); ss += __shfl_xor_sync(FULL, ss, 2);
                sd += __shfl_xor_sync(FULL, sd, 1); sd += __shfl_xor_sync(FULL, sd, 2);
                if (ok && ctid == 0) {
                    g_s1s[row * 8 + head0 + hh] = ss;
                    g_s1d[row * 8 + head0 + hh] = sd;
                }
            }
        }
    }
}

// ---------------- layer-1 aggregation: 2 warps/node, lane-parallel weights ----------------
// 4-edge chunks: lane (e=lane>>3, h=lane&7) computes one weight; features
// gathered as one uint4 (8 halves, single head eh=lane>>2) per edge per lane.
__global__ void __launch_bounds__(256) k_agg1(const float* __restrict__ b1) {
    __shared__ float red[4][32][9];    // [pair][lane][acc0..7, sm]
    int warp = threadIdx.x >> 5;
    int lane = threadIdx.x & 31;
    int pairi = warp >> 1;
    int half = warp & 1;
    int w = blockIdx.x * 4 + pairi;    // NN % 4 == 0
    int rs = g_rs[w];
    int deg = g_rs[w + 1] - rs;
    int lh = lane & 7;                 // head for weight computation
    int eh = lane >> 2;                // head owning this lane's 8 features

    float sdl = g_s1d[w * 8 + lh];

    int mid = deg >> 1;
    int jb = half ? mid : 0;
    int je = half ? deg : mid;

    float sm = 0.f;
    float acc[8] = {0.f, 0.f, 0.f, 0.f, 0.f, 0.f, 0.f, 0.f};
    int eoff = lane >> 3;              // which of the 4 chunk edges this lane weights
    for (int j = jb; j < je; j += 4) {
        int idx = j + eoff;
        bool valid = idx < je;
        int sE = valid ? g_csrc[rs + idx] : 0;
        float wl = valid ? lexp(g_s1s[sE * 8 + lh] + sdl) : 0.f;
        sm += wl;
        int s0 = __shfl_sync(FULL, sE, 0);
        int s1 = __shfl_sync(FULL, sE, 8);
        int s2 = __shfl_sync(FULL, sE, 16);
        int s3 = __shfl_sync(FULL, sE, 24);
        float w0 = __shfl_sync(FULL, wl, eh);
        float w1 = __shfl_sync(FULL, wl, 8 + eh);
        float w2 = __shfl_sync(FULL, wl, 16 + eh);
        float w3 = __shfl_sync(FULL, wl, 24 + eh);
        uint4 q0 = *(const uint4*)(g_h1h + s0 * HF + lane * 8);
        uint4 q1 = *(const uint4*)(g_h1h + s1 * HF + lane * 8);
        uint4 q2 = *(const uint4*)(g_h1h + s2 * HF + lane * 8);
        uint4 q3 = *(const uint4*)(g_h1h + s3 * HF + lane * 8);
        const __half2* h0 = (const __half2*)&q0;
        const __half2* h1 = (const __half2*)&q1;
        const __half2* h2 = (const __half2*)&q2;
        const __half2* h3 = (const __half2*)&q3;
#pragma unroll
        for (int p = 0; p < 4; p++) {
            float2 f0 = __half22float2(h0[p]);
            float2 f1 = __half22float2(h1[p]);
            float2 f2 = __half22float2(h2[p]);
            float2 f3 = __half22float2(h3[p]);
            acc[2 * p]     += w0 * f0.x + w1 * f1.x + w2 * f2.x + w3 * f3.x;
            acc[2 * p + 1] += w0 * f0.y + w1 * f1.y + w2 * f2.y + w3 * f3.y;
        }
    }

    if (half) {
#pragma unroll
        for (int k = 0; k < 8; k++) red[pairi][lane][k] = acc[k];
        red[pairi][lane][8] = sm;
    }
    __syncthreads();
    if (!half) {
#pragma unroll
        for (int k = 0; k < 8; k++) acc[k] += red[pairi][lane][k];
        sm += red[pairi][lane][8];
        // lanes h, h+8, h+16, h+24 hold disjoint edge subsets for head h
        sm += __shfl_xor_sync(FULL, sm, 8);
        sm += __shfl_xor_sync(FULL, sm, 16);
        float inv = 1.f / (sm + 1e-16f);
        float invk = __shfl_sync(FULL, inv, eh);   // lane eh has lh == eh
        int f = lane * 8;
        float4 bv0 = *(const float4*)&b1[f];
        float4 bv1 = *(const float4*)&b1[f + 4];
        float o[8];
        o[0] = acc[0] * invk + bv0.x; o[1] = acc[1] * invk + bv0.y;
        o[2] = acc[2] * invk + bv0.z; o[3] = acc[3] * invk + bv0.w;
        o[4] = acc[4] * invk + bv1.x; o[5] = acc[5] * invk + bv1.y;
        o[6] = acc[6] * invk + bv1.z; o[7] = acc[7] * invk + bv1.w;
        __half2 ph[4];
#pragma unroll
        for (int p = 0; p < 4; p++) {
            float e0 = o[2 * p]     > 0.f ? o[2 * p]     : expm1f(o[2 * p]);
            float e1 = o[2 * p + 1] > 0.f ? o[2 * p + 1] : expm1f(o[2 * p + 1]);
            ph[p] = __floats2half2_rn(e0, e1);
        }
        *(uint4*)(g_out1h + w * HF + f) = *(uint4*)ph;
    }
}

// ---------------- GEMM2 + layer-2 attention dots: warp per 2 nodes ----------------
__global__ void k_gemm2(const float* __restrict__ W2, const float* __restrict__ as2,
                        const float* __restrict__ ad2) {
    __shared__ float W2t[16][256];
    int t = threadIdx.x;
    for (int i = t; i < 4096; i += blockDim.x) {
        int k = i >> 4, c = i & 15;
        W2t[c][k] = W2[i];
    }
    __syncthreads();
    int lane = t & 31, wid = t >> 5;
    for (int n0 = blockIdx.x * 16 + wid * 2; n0 < NN; n0 += gridDim.x * 16) {
        const __half2* xa = (const __half2*)(g_out1h + n0 * HF);
        const __half2* xb = (const __half2*)(g_out1h + (n0 + 1) * HF);
        float accA[16], accB[16];
#pragma unroll
        for (int c = 0; c < 16; c++) { accA[c] = 0.f; accB[c] = 0.f; }
#pragma unroll
        for (int k = 0; k < 4; k++) {              // 4 x 32 half2 = 256 halves/row
            float2 fa = __half22float2(xa[k * 32 + lane]);
            float2 fb = __half22float2(xb[k * 32 + lane]);
            int fw = k * 64 + lane * 2;
#pragma unroll
            for (int c = 0; c < 16; c++) {
                float2 wv = *(const float2*)&W2t[c][fw];
                accA[c] += fa.x * wv.x + fa.y * wv.y;
                accB[c] += fb.x * wv.x + fb.y * wv.y;
            }
        }
#pragma unroll
        for (int c = 0; c < 16; c++)
#pragma unroll
            for (int off = 16; off; off >>= 1) {
                accA[c] += __shfl_xor_sync(FULL, accA[c], off);
                accB[c] += __shfl_xor_sync(FULL, accB[c], off);
            }
        {
            float h2v = accA[0];
#pragma unroll
            for (int c = 1; c < 16; c++)
                if ((lane & 15) == c) h2v = accA[c];
            if (lane < 16) g_h2[n0 * CC + lane] = h2v;
            float ps = (lane < 16) ? h2v * as2[lane] : 0.f;
            float pd = (lane < 16) ? h2v * ad2[lane] : 0.f;
#pragma unroll
            for (int off = 16; off; off >>= 1) {
                ps += __shfl_xor_sync(FULL, ps, off);
                pd += __shfl_xor_sync(FULL, pd, off);
            }
            if (lane == 0) { g_s2s[n0] = ps; g_s2d[n0] = pd; }
        }
        {
            float h2v = accB[0];
#pragma unroll
            for (int c = 1; c < 16; c++)
                if ((lane & 15) == c) h2v = accB[c];
            if (lane < 16) g_h2[(n0 + 1) * CC + lane] = h2v;
            float ps = (lane < 16) ? h2v * as2[lane] : 0.f;
            float pd = (lane < 16) ? h2v * ad2[lane] : 0.f;
#pragma unroll
            for (int off = 16; off; off >>= 1) {
                ps += __shfl_xor_sync(FULL, ps, off);
                pd += __shfl_xor_sync(FULL, pd, off);
            }
            if (lane == 0) { g_s2s[n0 + 1] = ps; g_s2d[n0 + 1] = pd; }
        }
    }
}

// ---------------- layer-2 aggregation: inline edge weights ----------------
__global__ void __launch_bounds__(256) k_agg2(const float* __restrict__ b2,
                                              float* __restrict__ out) {
    int gt = blockIdx.x * blockDim.x + threadIdx.x;
    int w = gt >> 5;
    int lane = threadIdx.x & 31;
    if (w >= NN) return;
    int rs = g_rs[w];
    int deg = g_rs[w + 1] - rs;
    int half = lane >> 4, l15 = lane & 15;

    float sd = g_s2d[w];
    float sm = 0.f;
    float acc = 0.f;
    for (int j = half; j < deg; j += 2) {
        int s = g_csrc[rs + j];
        float wv = lexp(g_s2s[s] + sd);
        sm += wv;
        acc += wv * g_h2[s * CC + l15];
    }
    acc += __shfl_xor_sync(FULL, acc, 16);
    sm += __shfl_xor_sync(FULL, sm, 16);
    float inv = 1.f / (sm + 1e-16f);
    if (lane < 16) out[w * CC + l15] = acc * inv + b2[l15];
}

// ---------------- launch ----------------
extern "C" void kernel_launch(void* const* d_in, const int* in_sizes, int n_in,
                              void* d_out, int out_size) {
    const float* x = (const float*)d_in[0];
    const int* ei = (const int*)d_in[1];
    const float* W1 = (const float*)d_in[2];
    const float* as1 = (const float*)d_in[3];
    const float* ad1 = (const float*)d_in[4];
    const float* b1 = (const float*)d_in[5];
    const float* W2 = (const float*)d_in[6];
    const float* as2 = (const float*)d_in[7];
    const float* ad2 = (const float*)d_in[8];
    const float* b2 = (const float*)d_in[9];
    float* out = (float*)d_out;

    // CSR build (gemm1 placed 4th so ncu's skip window keeps capturing it)
    k_zero<<<(NN + 255) / 256, 256>>>();
    k_hist<<<(NE + 255) / 256, 256>>>(ei);
    k_scanA<<<NB_SCAN, 1024>>>();
    k_gemm1<<<dim3((NN + 127) / 128, 2), 256>>>(x, W1, as1, ad1);
    k_scanB<<<1, 128>>>();
    k_scanC<<<(NN + 255) / 256, 256>>>();
    k_scatter<<<(NE + 255) / 256, 256>>>(ei);

    // layer 1: 2 warps per node, lane-parallel weights
    k_agg1<<<NN / 4, 256>>>(b1);

    // layer 2
    k_gemm2<<<1024, 256>>>(W2, as2, ad2);
    k_agg2<<<(NN * 32 + 255) / 256, 256>>>(b2, out);
}